// round 6
// baseline (speedup 1.0000x reference)
#include <cuda_runtime.h>
#include <cstdint>

// ---------------------------------------------------------------------------
// Problem constants
// ---------------------------------------------------------------------------
#define T_TOKENS 4096
#define DDIM 1024
#define FDIM 4096
#define NEXP 8
#define BM 128
#define BN 128
#define BK 32
#define MAX_MT 72
#define ROWS_CAP (MAX_MT * 128)

// ---------------------------------------------------------------------------
// Device scratch
// ---------------------------------------------------------------------------
__device__ int   g_cnt[NEXP];
__device__ int   g_cur[NEXP];
__device__ int   g_done;
__device__ int   g_nmt;
__device__ int   g_tile_e[MAX_MT];
__device__ int   g_tile_r[MAX_MT];
__device__ int   g_row_token[ROWS_CAP];
__device__ int   g_tok_e[T_TOKENS * 2];
__device__ int   g_tok_row[T_TOKENS * 2];
__device__ float g_tok_w[T_TOKENS * 2];
__device__ float g_H[(size_t)ROWS_CAP * FDIM];
__device__ float g_Y[(size_t)ROWS_CAP * DDIM];
__device__ float g_xt[(size_t)T_TOKENS * DDIM];
__device__ float g_w1t[(size_t)NEXP * DDIM * FDIM];
__device__ float g_w3t[(size_t)NEXP * DDIM * FDIM];
__device__ float g_w2t[(size_t)NEXP * DDIM * FDIM];

// ---------------------------------------------------------------------------
// Helpers
// ---------------------------------------------------------------------------
__device__ __forceinline__ uint32_t smem_u32(const void* p) {
    uint32_t a;
    asm("{ .reg .u64 t; cvta.to.shared.u64 t, %1; cvt.u32.u64 %0, t; }" : "=r"(a) : "l"(p));
    return a;
}
__device__ __forceinline__ uint32_t tf32u(float f) {
    uint32_t u = __float_as_uint(f);
    asm("cvt.rna.tf32.f32 %0, %0;" : "+r"(u));
    return u;
}
__device__ __forceinline__ uint32_t lds32(uint32_t a) {
    uint32_t v;
    asm volatile("ld.shared.b32 %0, [%1];" : "=r"(v) : "r"(a));
    return v;
}
__device__ __forceinline__ void sts128f(uint32_t a, float x, float y, float z, float w) {
    asm volatile("st.shared.v4.f32 [%0], {%1,%2,%3,%4};" :: "r"(a), "f"(x), "f"(y), "f"(z), "f"(w));
}
__device__ __forceinline__ float4 lds128f(uint32_t a) {
    float4 v;
    asm volatile("ld.shared.v4.f32 {%0,%1,%2,%3}, [%4];"
                 : "=f"(v.x), "=f"(v.y), "=f"(v.z), "=f"(v.w) : "r"(a));
    return v;
}
__device__ __forceinline__ void mma8(float* d, const uint32_t* a, uint32_t b0, uint32_t b1) {
    asm volatile(
        "mma.sync.aligned.m16n8k8.row.col.f32.tf32.tf32.f32 "
        "{%0,%1,%2,%3}, {%4,%5,%6,%7}, {%8,%9}, {%0,%1,%2,%3};"
        : "+f"(d[0]), "+f"(d[1]), "+f"(d[2]), "+f"(d[3])
        : "r"(a[0]), "r"(a[1]), "r"(a[2]), "r"(a[3]), "r"(b0), "r"(b1));
}
#define CP_ASYNC16(dst, src) \
    asm volatile("cp.async.cg.shared.global [%0], [%1], 16;" :: "r"(dst), "l"(src))
#define CP_COMMIT() asm volatile("cp.async.commit_group;" ::: "memory")
#define CP_WAIT1()  asm volatile("cp.async.wait_group 1;" ::: "memory")
#define CP_WAIT0()  asm volatile("cp.async.wait_group 0;" ::: "memory")

// Region: 128 rows x 32 floats = two 8KB sub-tiles of [row][16 floats]
// (64B rows, SW64 swizzle). Conflict-free (verified R3-R5).
#define REGION_SZ 16384
#define STAGE1_SZ 49152   // A + B1 + B3
#define STAGE2_SZ 32768   // A + B
#define SMEM1_SZ (1024 + 3 * STAGE1_SZ)
#define SMEM2_SZ (1024 + 3 * STAGE2_SZ)

// ---------------------------------------------------------------------------
// L1: convx + init
// ---------------------------------------------------------------------------
__global__ void convx_init_kernel(const float* __restrict__ x) {
    int i = blockIdx.x * blockDim.x + threadIdx.x;
    if (blockIdx.x == 0) {
        if (threadIdx.x < NEXP) g_cnt[threadIdx.x] = 0;
        if (threadIdx.x == NEXP) g_done = 0;
    }
    float4 v = ((const float4*)x)[i];
    uint4 o;
    o.x = tf32u(v.x); o.y = tf32u(v.y); o.z = tf32u(v.z); o.w = tf32u(v.w);
    ((uint4*)g_xt)[i] = o;
}

// ---------------------------------------------------------------------------
// L2: fused router + scan + scatter (last-CTA pattern)
// ---------------------------------------------------------------------------
__global__ void __launch_bounds__(256)
router_fused_kernel(const float* __restrict__ x, const float* __restrict__ rw,
                    const float* __restrict__ rb) {
    __shared__ float s_rw[NEXP * DDIM];
    __shared__ int s_last;
    const int tid = threadIdx.x, wid = tid >> 5, lane = tid & 31;

    for (int i = tid; i < NEXP * DDIM / 2; i += 256)
        ((float2*)s_rw)[i] = ((const float2*)rw)[i];
    __syncthreads();

    const int tbase = blockIdx.x * 128 + wid * 16;
    for (int j = 0; j < 16; j++) {
        const int t = tbase + j;
        const float* xt = x + (size_t)t * DDIM;
        float acc[NEXP];
#pragma unroll
        for (int e = 0; e < NEXP; e++) acc[e] = 0.f;
        for (int i = lane; i < DDIM; i += 32) {
            float xv = xt[i];
#pragma unroll
            for (int e = 0; e < NEXP; e++) acc[e] += xv * s_rw[e * DDIM + i];
        }
#pragma unroll
        for (int off = 16; off; off >>= 1)
#pragma unroll
            for (int e = 0; e < NEXP; e++) acc[e] += __shfl_xor_sync(0xffffffffu, acc[e], off);
        if (lane == 0) {
#pragma unroll
            for (int e = 0; e < NEXP; e++) acc[e] += rb[e];
            int e0 = 0; float l0 = acc[0];
#pragma unroll
            for (int e = 1; e < NEXP; e++) if (acc[e] > l0) { l0 = acc[e]; e0 = e; }
            int e1 = (e0 == 0) ? 1 : 0; float l1 = acc[e1];
#pragma unroll
            for (int e = 0; e < NEXP; e++)
                if (e != e0 && acc[e] > l1) { l1 = acc[e]; e1 = e; }
            float w0 = 1.f / (1.f + __expf(l1 - l0));
            g_tok_e[2 * t] = e0;  g_tok_e[2 * t + 1] = e1;
            g_tok_w[2 * t] = w0;  g_tok_w[2 * t + 1] = 1.f - w0;
            atomicAdd(&g_cnt[e0], 1);
            atomicAdd(&g_cnt[e1], 1);
        }
    }

    __syncthreads();
    if (tid == 0) {
        __threadfence();
        int v = atomicAdd(&g_done, 1);
        s_last = (v == (int)gridDim.x - 1);
    }
    __syncthreads();
    if (!s_last) return;
    __threadfence();

    if (tid == 0) {
        int base = 0, nt = 0;
        for (int e = 0; e < NEXP; e++) {
            g_cur[e] = base;
            int tiles = (g_cnt[e] + 127) >> 7;
            for (int i = 0; i < tiles; i++) { g_tile_e[nt] = e; g_tile_r[nt] = base + i * 128; nt++; }
            base += tiles << 7;
        }
        g_nmt = nt;
        g_done = 0;
    }
    __syncthreads();

    for (int t = tid; t < T_TOKENS; t += 256) {
#pragma unroll
        for (int k = 0; k < 2; k++) {
            int e = g_tok_e[2 * t + k];
            int r = atomicAdd(&g_cur[e], 1);
            g_row_token[r] = t;
            g_tok_row[2 * t + k] = r;
        }
    }
}

// ---------------------------------------------------------------------------
// L3/L5: weight transposes (+tf32 round)
// ---------------------------------------------------------------------------
__global__ void transpose13_kernel(const float* __restrict__ w1, const float* __restrict__ w3,
                                   float* __restrict__ w1t, float* __restrict__ w3t) {
    __shared__ float t[32][33];
    const int zz = blockIdx.z;
    const float* src = (zz < NEXP) ? w1 : w3;
    float* dst = (zz < NEXP) ? w1t : w3t;
    const size_t mo = (size_t)(zz & 7) * DDIM * FDIM;
    const int c0 = blockIdx.x * 32, r0 = blockIdx.y * 32;
    const int tx = threadIdx.x, ty = threadIdx.y;
#pragma unroll
    for (int i = 0; i < 32; i += 8)
        t[ty + i][tx] = src[mo + (size_t)(r0 + ty + i) * FDIM + c0 + tx];
    __syncthreads();
#pragma unroll
    for (int i = 0; i < 32; i += 8)
        dst[mo + (size_t)(c0 + ty + i) * DDIM + r0 + tx] = __uint_as_float(tf32u(t[tx][ty + i]));
}

__global__ void transpose2_kernel(const float* __restrict__ src, float* __restrict__ dst) {
    __shared__ float t[32][33];
    const size_t mo = (size_t)blockIdx.z * DDIM * FDIM;
    const int c0 = blockIdx.x * 32, r0 = blockIdx.y * 32;
    const int tx = threadIdx.x, ty = threadIdx.y;
#pragma unroll
    for (int i = 0; i < 32; i += 8)
        t[ty + i][tx] = src[mo + (size_t)(r0 + ty + i) * DDIM + c0 + tx];
    __syncthreads();
#pragma unroll
    for (int i = 0; i < 32; i += 8)
        dst[mo + (size_t)(c0 + ty + i) * FDIM + r0 + tx] = __uint_as_float(tf32u(t[tx][ty + i]));
}

// ---------------------------------------------------------------------------
// L4: grouped GEMM1 — H = silu(X@w1) * (X@w3)
// 512 threads: warps 0-7 compute U=X@w1, warps 8-15 compute V=X@w3.
// Each group: 2Mx4N warps, warp tile 64x32, 64 accs/thread.
// ---------------------------------------------------------------------------
__global__ void __launch_bounds__(512, 1)
gemm1_kernel() {
    if (blockIdx.x >= g_nmt) return;
    extern __shared__ char smem[];
    const uint32_t sb = smem_u32(smem);
    const int tid = threadIdx.x, wid = tid >> 5, lane = tid & 31;
    const int group = wid >> 3, wg = wid & 7;
    const int wm = wg >> 2, wn = wg & 3;
    const int r4 = lane >> 2, c4 = lane & 3;
    const uint32_t xa = (uint32_t)((r4 & 6) << 3);

    const int e  = g_tile_e[blockIdx.x];
    const int r0 = g_tile_r[blockIdx.x];
    const int n0 = blockIdx.y * BN;

    int* s_tok = (int*)smem;
    if (tid < 128) {
        int t = g_row_token[r0 + tid];
        s_tok[tid] = ((unsigned)t < T_TOKENS) ? t : 0;
    }
    __syncthreads();

    const float* w1e = g_w1t + (size_t)e * FDIM * DDIM + (size_t)n0 * DDIM;
    const float* w3e = g_w3t + (size_t)e * FDIM * DDIM + (size_t)n0 * DDIM;

    // staging: 512 threads x 2 chunks per region
    const char* srcA[2]; const char* srcB1[2]; const char* srcB3[2];
    uint32_t dOf[2];
#pragma unroll
    for (int i = 0; i < 2; i++) {
        int idx = tid + i * 512;
        int row = idx >> 3, c = idx & 7;
        dOf[i] = (uint32_t)((c >> 2) * 8192 + row * 64 + (((c & 3) * 16) ^ ((row & 6) << 3)));
        srcA[i]  = (const char*)(g_xt + (size_t)s_tok[row] * DDIM + c * 4);
        srcB1[i] = (const char*)(w1e + (size_t)row * DDIM + c * 4);
        srcB3[i] = (const char*)(w3e + (size_t)row * DDIM + c * 4);
    }

    float acc[4][4][4];
#pragma unroll
    for (int i = 0; i < 4; i++)
#pragma unroll
        for (int j = 0; j < 4; j++)
#pragma unroll
            for (int q = 0; q < 4; q++) acc[i][j][q] = 0.f;

    const int KS = DDIM / BK;   // 32
    const uint32_t bsel = (uint32_t)(16384 + group * 16384);   // B1 or B3 region

#define G1_ISSUE(s)                                                            \
    do {                                                                       \
        uint32_t base_ = sb + 1024 + ((s) % 3) * STAGE1_SZ;                    \
        size_t off_ = (size_t)(s) * 128;                                       \
        _Pragma("unroll")                                                      \
        for (int i_ = 0; i_ < 2; i_++) {                                       \
            CP_ASYNC16(base_ + dOf[i_],         srcA[i_]  + off_);             \
            CP_ASYNC16(base_ + 16384 + dOf[i_], srcB1[i_] + off_);             \
            CP_ASYNC16(base_ + 32768 + dOf[i_], srcB3[i_] + off_);             \
        }                                                                      \
    } while (0)

    G1_ISSUE(0); CP_COMMIT();
    G1_ISSUE(1); CP_COMMIT();

    for (int ks = 0; ks < KS; ks++) {
        CP_WAIT1();
        __syncthreads();
        if (ks + 2 < KS) G1_ISSUE(ks + 2);
        CP_COMMIT();

        const uint32_t st = sb + 1024 + (ks % 3) * STAGE1_SZ;
#pragma unroll
        for (int k8 = 0; k8 < 4; k8++) {
            const uint32_t sub = (uint32_t)((k8 >> 1) * 8192);
            const uint32_t sA = st + sub;
            const uint32_t sB = st + bsel + sub;
            const uint32_t k0 = (uint32_t)((((k8 & 1) * 8) + c4) * 4);
            const uint32_t k1 = k0 + 16;
            uint32_t a[4][4];
#pragma unroll
            for (int mt = 0; mt < 4; mt++) {
                uint32_t rowb = sA + (uint32_t)((wm * 64 + mt * 16 + r4) * 64);
                a[mt][0] = lds32(rowb + (k0 ^ xa));
                a[mt][1] = lds32(rowb + 512 + (k0 ^ xa));
                a[mt][2] = lds32(rowb + (k1 ^ xa));
                a[mt][3] = lds32(rowb + 512 + (k1 ^ xa));
            }
#pragma unroll
            for (int nt = 0; nt < 4; nt++) {
                uint32_t nrow = sB + (uint32_t)((wn * 32 + nt * 8 + r4) * 64);
                uint32_t b0 = lds32(nrow + (k0 ^ xa));
                uint32_t b1 = lds32(nrow + (k1 ^ xa));
#pragma unroll
                for (int mt = 0; mt < 4; mt++) mma8(acc[mt][nt], a[mt], b0, b1);
            }
        }
    }

    // drain async copies, then reuse stage region as U/V exchange buffer
    CP_WAIT0();
    __syncthreads();
    const uint32_t ex = sb + 1024;
    if (group == 1) {
#pragma unroll
        for (int mt = 0; mt < 4; mt++)
#pragma unroll
            for (int nt = 0; nt < 4; nt++)
                sts128f(ex + (uint32_t)(((wg * 16 + mt * 4 + nt) * 32 + lane) * 16),
                        acc[mt][nt][0], acc[mt][nt][1], acc[mt][nt][2], acc[mt][nt][3]);
    }
    __syncthreads();
    if (group == 0) {
#pragma unroll
        for (int mt = 0; mt < 4; mt++) {
#pragma unroll
            for (int nt = 0; nt < 4; nt++) {
                float4 v = lds128f(ex + (uint32_t)(((wg * 16 + mt * 4 + nt) * 32 + lane) * 16));
                int r = r0 + wm * 64 + mt * 16 + r4;
                int cgl = n0 + wn * 32 + nt * 8 + 2 * c4;
                float u0 = acc[mt][nt][0], u1 = acc[mt][nt][1];
                float u2 = acc[mt][nt][2], u3 = acc[mt][nt][3];
                float2 o0, o1;
                o0.x = __uint_as_float(tf32u(u0 / (1.f + __expf(-u0)) * v.x));
                o0.y = __uint_as_float(tf32u(u1 / (1.f + __expf(-u1)) * v.y));
                o1.x = __uint_as_float(tf32u(u2 / (1.f + __expf(-u2)) * v.z));
                o1.y = __uint_as_float(tf32u(u3 / (1.f + __expf(-u3)) * v.w));
                *(float2*)(g_H + (size_t)r * FDIM + cgl) = o0;
                *(float2*)(g_H + (size_t)(r + 8) * FDIM + cgl) = o1;
            }
        }
    }
}

// ---------------------------------------------------------------------------
// L6: grouped GEMM2 — Y = H @ w2
// 512 threads, 4Mx4N warps, warp tile 32x32, 32 accs/thread.
// ---------------------------------------------------------------------------
__global__ void __launch_bounds__(512, 1)
gemm2_kernel() {
    if (blockIdx.x >= g_nmt) return;
    extern __shared__ char smem[];
    const uint32_t sb = smem_u32(smem);
    const int tid = threadIdx.x, wid = tid >> 5, lane = tid & 31;
    const int wm = wid >> 2, wn = wid & 3;
    const int r4 = lane >> 2, c4 = lane & 3;
    const uint32_t xa = (uint32_t)((r4 & 6) << 3);

    const int e  = g_tile_e[blockIdx.x];
    const int r0 = g_tile_r[blockIdx.x];
    const int n0 = blockIdx.y * BN;

    const float* w2e = g_w2t + (size_t)e * DDIM * FDIM + (size_t)n0 * FDIM;

    const char* srcA[2]; const char* srcB[2];
    uint32_t dOf[2];
#pragma unroll
    for (int i = 0; i < 2; i++) {
        int idx = tid + i * 512;
        int row = idx >> 3, c = idx & 7;
        dOf[i] = (uint32_t)((c >> 2) * 8192 + row * 64 + (((c & 3) * 16) ^ ((row & 6) << 3)));
        srcA[i] = (const char*)(g_H + (size_t)(r0 + row) * FDIM + c * 4);
        srcB[i] = (const char*)(w2e + (size_t)row * FDIM + c * 4);
    }

    float acc[2][4][4];
#pragma unroll
    for (int i = 0; i < 2; i++)
#pragma unroll
        for (int j = 0; j < 4; j++)
#pragma unroll
            for (int q = 0; q < 4; q++) acc[i][j][q] = 0.f;

    const int KS = FDIM / BK;   // 128

#define G2_ISSUE(s)                                                            \
    do {                                                                       \
        uint32_t base_ = sb + 1024 + ((s) % 3) * STAGE2_SZ;                    \
        size_t off_ = (size_t)(s) * 128;                                       \
        _Pragma("unroll")                                                      \
        for (int i_ = 0; i_ < 2; i_++) {                                       \
            CP_ASYNC16(base_ + dOf[i_],         srcA[i_] + off_);              \
            CP_ASYNC16(base_ + 16384 + dOf[i_], srcB[i_] + off_);              \
        }                                                                      \
    } while (0)

    G2_ISSUE(0); CP_COMMIT();
    G2_ISSUE(1); CP_COMMIT();

    for (int ks = 0; ks < KS; ks++) {
        CP_WAIT1();
        __syncthreads();
        if (ks + 2 < KS) G2_ISSUE(ks + 2);
        CP_COMMIT();

        const uint32_t st = sb + 1024 + (ks % 3) * STAGE2_SZ;
#pragma unroll
        for (int k8 = 0; k8 < 4; k8++) {
            const uint32_t sub = (uint32_t)((k8 >> 1) * 8192);
            const uint32_t sA = st + sub;
            const uint32_t sB = st + 16384 + sub;
            const uint32_t k0 = (uint32_t)((((k8 & 1) * 8) + c4) * 4);
            const uint32_t k1 = k0 + 16;
            uint32_t a[2][4];
#pragma unroll
            for (int mt = 0; mt < 2; mt++) {
                uint32_t rowb = sA + (uint32_t)((wm * 32 + mt * 16 + r4) * 64);
                a[mt][0] = lds32(rowb + (k0 ^ xa));
                a[mt][1] = lds32(rowb + 512 + (k0 ^ xa));
                a[mt][2] = lds32(rowb + (k1 ^ xa));
                a[mt][3] = lds32(rowb + 512 + (k1 ^ xa));
            }
#pragma unroll
            for (int nt = 0; nt < 4; nt++) {
                uint32_t nrow = sB + (uint32_t)((wn * 32 + nt * 8 + r4) * 64);
                uint32_t b0 = lds32(nrow + (k0 ^ xa));
                uint32_t b1 = lds32(nrow + (k1 ^ xa));
#pragma unroll
                for (int mt = 0; mt < 2; mt++) mma8(acc[mt][nt], a[mt], b0, b1);
            }
        }
    }

#pragma unroll
    for (int mt = 0; mt < 2; mt++) {
#pragma unroll
        for (int nt = 0; nt < 4; nt++) {
#pragma unroll
            for (int half = 0; half < 2; half++) {
                int r = r0 + wm * 32 + mt * 16 + r4 + half * 8;
                int cgl = n0 + wn * 32 + nt * 8 + 2 * c4;
                float2 o;
                o.x = acc[mt][nt][2 * half];
                o.y = acc[mt][nt][2 * half + 1];
                *(float2*)(g_Y + (size_t)r * DDIM + cgl) = o;
            }
        }
    }
}

// ---------------------------------------------------------------------------
// L7: combine
// ---------------------------------------------------------------------------
__global__ void combine_kernel(float* __restrict__ out) {
    int t = blockIdx.x;
    int d = threadIdx.x * 4;
    float w0 = g_tok_w[2 * t], w1v = g_tok_w[2 * t + 1];
    int   r0 = g_tok_row[2 * t], r1 = g_tok_row[2 * t + 1];
    const float4 a = *(const float4*)(g_Y + (size_t)r0 * DDIM + d);
    const float4 b = *(const float4*)(g_Y + (size_t)r1 * DDIM + d);
    float4 o;
    o.x = w0 * a.x + w1v * b.x;
    o.y = w0 * a.y + w1v * b.y;
    o.z = w0 * a.z + w1v * b.z;
    o.w = w0 * a.w + w1v * b.w;
    *(float4*)(out + (size_t)t * DDIM + d) = o;
}

// ---------------------------------------------------------------------------
// Launcher — gemm1 stays the 4th launch (profiler target)
// ---------------------------------------------------------------------------
extern "C" void kernel_launch(void* const* d_in, const int* in_sizes, int n_in,
                              void* d_out, int out_size) {
    const float* x  = (const float*)d_in[0];
    const float* rw = (const float*)d_in[1];
    const float* rb = (const float*)d_in[2];
    const float* w1 = (const float*)d_in[3];
    const float* w2 = (const float*)d_in[4];
    const float* w3 = (const float*)d_in[5];
    float* out = (float*)d_out;

    cudaFuncSetAttribute(gemm1_kernel, cudaFuncAttributeMaxDynamicSharedMemorySize, SMEM1_SZ);
    cudaFuncSetAttribute(gemm2_kernel, cudaFuncAttributeMaxDynamicSharedMemorySize, SMEM2_SZ);

    float *w1t, *w3t, *w2t;
    cudaGetSymbolAddress((void**)&w1t, g_w1t);
    cudaGetSymbolAddress((void**)&w3t, g_w3t);
    cudaGetSymbolAddress((void**)&w2t, g_w2t);

    convx_init_kernel<<<(T_TOKENS * DDIM / 4) / 256, 256>>>(x);
    router_fused_kernel<<<32, 256>>>(x, rw, rb);
    transpose13_kernel<<<dim3(FDIM / 32, DDIM / 32, 2 * NEXP), dim3(32, 8)>>>(w1, w3, w1t, w3t);
    gemm1_kernel<<<dim3(MAX_MT, FDIM / BN), 512, SMEM1_SZ>>>();
    transpose2_kernel<<<dim3(DDIM / 32, FDIM / 32, NEXP), dim3(32, 8)>>>(w2, w2t);
    gemm2_kernel<<<dim3(MAX_MT, DDIM / BN), 512, SMEM2_SZ>>>();
    combine_kernel<<<T_TOKENS, 256>>>(out);
}

// round 7
// speedup vs baseline: 1.0964x; 1.0964x over previous
#include <cuda_runtime.h>
#include <cstdint>

// ---------------------------------------------------------------------------
// Problem constants
// ---------------------------------------------------------------------------
#define T_TOKENS 4096
#define DDIM 1024
#define FDIM 4096
#define NEXP 8
#define BM 128
#define BN 128
#define BK 32
#define MAX_MT 72
#define ROWS_CAP (MAX_MT * 128)

// ---------------------------------------------------------------------------
// Device scratch
// ---------------------------------------------------------------------------
__device__ int   g_cnt[NEXP];
__device__ int   g_cur[NEXP];
__device__ int   g_done;
__device__ int   g_nmt;
__device__ int   g_tile_e[MAX_MT];
__device__ int   g_tile_r[MAX_MT];
__device__ int   g_row_token[ROWS_CAP];
__device__ int   g_tok_e[T_TOKENS * 2];
__device__ int   g_tok_row[T_TOKENS * 2];
__device__ float g_tok_w[T_TOKENS * 2];
__device__ float g_H[(size_t)ROWS_CAP * FDIM];
__device__ float g_Y[(size_t)ROWS_CAP * DDIM];
__device__ float g_xt[(size_t)T_TOKENS * DDIM];
__device__ float g_w1t[(size_t)NEXP * DDIM * FDIM];
__device__ float g_w3t[(size_t)NEXP * DDIM * FDIM];
__device__ float g_w2t[(size_t)NEXP * DDIM * FDIM];

// ---------------------------------------------------------------------------
// Helpers
// ---------------------------------------------------------------------------
__device__ __forceinline__ uint32_t smem_u32(const void* p) {
    uint32_t a;
    asm("{ .reg .u64 t; cvta.to.shared.u64 t, %1; cvt.u32.u64 %0, t; }" : "=r"(a) : "l"(p));
    return a;
}
__device__ __forceinline__ uint32_t tf32u(float f) {
    uint32_t u = __float_as_uint(f);
    asm("cvt.rna.tf32.f32 %0, %0;" : "+r"(u));
    return u;
}
__device__ __forceinline__ uint32_t lds32(uint32_t a) {
    uint32_t v;
    asm volatile("ld.shared.b32 %0, [%1];" : "=r"(v) : "r"(a));
    return v;
}
__device__ __forceinline__ void mma8(float* d, const uint32_t* a, uint32_t b0, uint32_t b1) {
    asm volatile(
        "mma.sync.aligned.m16n8k8.row.col.f32.tf32.tf32.f32 "
        "{%0,%1,%2,%3}, {%4,%5,%6,%7}, {%8,%9}, {%0,%1,%2,%3};"
        : "+f"(d[0]), "+f"(d[1]), "+f"(d[2]), "+f"(d[3])
        : "r"(a[0]), "r"(a[1]), "r"(a[2]), "r"(a[3]), "r"(b0), "r"(b1));
}
#define CP_ASYNC16(dst, src) \
    asm volatile("cp.async.cg.shared.global [%0], [%1], 16;" :: "r"(dst), "l"(src))
#define CP_COMMIT() asm volatile("cp.async.commit_group;" ::: "memory")
#define CP_WAIT1()  asm volatile("cp.async.wait_group 1;" ::: "memory")

// Region: 128 rows x 32 floats = two 8KB sub-tiles of [row][16 floats]
// (64B rows, SW64 swizzle). Conflict-free (verified R3-R6).
#define STAGE1_SZ 49152   // A + B1 + B3
#define STAGE2_SZ 32768   // A + B
#define SMEM1_SZ (1024 + 3 * STAGE1_SZ)
#define SMEM2_SZ (1024 + 3 * STAGE2_SZ)

// ---------------------------------------------------------------------------
// L1: convx + init
// ---------------------------------------------------------------------------
__global__ void convx_init_kernel(const float* __restrict__ x) {
    int i = blockIdx.x * blockDim.x + threadIdx.x;
    if (blockIdx.x == 0) {
        if (threadIdx.x < NEXP) g_cnt[threadIdx.x] = 0;
        if (threadIdx.x == NEXP) g_done = 0;
    }
    float4 v = ((const float4*)x)[i];
    uint4 o;
    o.x = tf32u(v.x); o.y = tf32u(v.y); o.z = tf32u(v.z); o.w = tf32u(v.w);
    ((uint4*)g_xt)[i] = o;
}

// ---------------------------------------------------------------------------
// L2: fused router + scan + scatter (last-CTA pattern); 64 CTAs
// ---------------------------------------------------------------------------
__global__ void __launch_bounds__(256)
router_fused_kernel(const float* __restrict__ x, const float* __restrict__ rw,
                    const float* __restrict__ rb) {
    __shared__ float s_rw[NEXP * DDIM];
    __shared__ int s_last;
    const int tid = threadIdx.x, wid = tid >> 5, lane = tid & 31;

    for (int i = tid; i < NEXP * DDIM / 2; i += 256)
        ((float2*)s_rw)[i] = ((const float2*)rw)[i];
    __syncthreads();

    const int tbase = blockIdx.x * 64 + wid * 8;
    for (int j = 0; j < 8; j++) {
        const int t = tbase + j;
        const float* xt = x + (size_t)t * DDIM;
        float acc[NEXP];
#pragma unroll
        for (int e = 0; e < NEXP; e++) acc[e] = 0.f;
        for (int i = lane; i < DDIM; i += 32) {
            float xv = xt[i];
#pragma unroll
            for (int e = 0; e < NEXP; e++) acc[e] += xv * s_rw[e * DDIM + i];
        }
#pragma unroll
        for (int off = 16; off; off >>= 1)
#pragma unroll
            for (int e = 0; e < NEXP; e++) acc[e] += __shfl_xor_sync(0xffffffffu, acc[e], off);
        if (lane == 0) {
#pragma unroll
            for (int e = 0; e < NEXP; e++) acc[e] += rb[e];
            int e0 = 0; float l0 = acc[0];
#pragma unroll
            for (int e = 1; e < NEXP; e++) if (acc[e] > l0) { l0 = acc[e]; e0 = e; }
            int e1 = (e0 == 0) ? 1 : 0; float l1 = acc[e1];
#pragma unroll
            for (int e = 0; e < NEXP; e++)
                if (e != e0 && acc[e] > l1) { l1 = acc[e]; e1 = e; }
            float w0 = 1.f / (1.f + __expf(l1 - l0));
            g_tok_e[2 * t] = e0;  g_tok_e[2 * t + 1] = e1;
            g_tok_w[2 * t] = w0;  g_tok_w[2 * t + 1] = 1.f - w0;
            atomicAdd(&g_cnt[e0], 1);
            atomicAdd(&g_cnt[e1], 1);
        }
    }

    __syncthreads();
    if (tid == 0) {
        __threadfence();
        int v = atomicAdd(&g_done, 1);
        s_last = (v == (int)gridDim.x - 1);
    }
    __syncthreads();
    if (!s_last) return;
    __threadfence();

    if (tid == 0) {
        int base = 0, nt = 0;
        for (int e = 0; e < NEXP; e++) {
            g_cur[e] = base;
            int tiles = (g_cnt[e] + 127) >> 7;
            for (int i = 0; i < tiles; i++) { g_tile_e[nt] = e; g_tile_r[nt] = base + i * 128; nt++; }
            base += tiles << 7;
        }
        g_nmt = nt;
        g_done = 0;
    }
    __syncthreads();

    for (int t = tid; t < T_TOKENS; t += 256) {
#pragma unroll
        for (int k = 0; k < 2; k++) {
            int e = g_tok_e[2 * t + k];
            int r = atomicAdd(&g_cur[e], 1);
            g_row_token[r] = t;
            g_tok_row[2 * t + k] = r;
        }
    }
}

// ---------------------------------------------------------------------------
// Weight transposes (+tf32 round)  — run on a forked stream
// ---------------------------------------------------------------------------
__global__ void transpose13_kernel(const float* __restrict__ w1, const float* __restrict__ w3,
                                   float* __restrict__ w1t, float* __restrict__ w3t) {
    __shared__ float t[32][33];
    const int zz = blockIdx.z;
    const float* src = (zz < NEXP) ? w1 : w3;
    float* dst = (zz < NEXP) ? w1t : w3t;
    const size_t mo = (size_t)(zz & 7) * DDIM * FDIM;
    const int c0 = blockIdx.x * 32, r0 = blockIdx.y * 32;
    const int tx = threadIdx.x, ty = threadIdx.y;
#pragma unroll
    for (int i = 0; i < 32; i += 8)
        t[ty + i][tx] = src[mo + (size_t)(r0 + ty + i) * FDIM + c0 + tx];
    __syncthreads();
#pragma unroll
    for (int i = 0; i < 32; i += 8)
        dst[mo + (size_t)(c0 + ty + i) * DDIM + r0 + tx] = __uint_as_float(tf32u(t[tx][ty + i]));
}

__global__ void transpose2_kernel(const float* __restrict__ src, float* __restrict__ dst) {
    __shared__ float t[32][33];
    const size_t mo = (size_t)blockIdx.z * DDIM * FDIM;
    const int c0 = blockIdx.x * 32, r0 = blockIdx.y * 32;
    const int tx = threadIdx.x, ty = threadIdx.y;
#pragma unroll
    for (int i = 0; i < 32; i += 8)
        t[ty + i][tx] = src[mo + (size_t)(r0 + ty + i) * DDIM + c0 + tx];
    __syncthreads();
#pragma unroll
    for (int i = 0; i < 32; i += 8)
        dst[mo + (size_t)(c0 + ty + i) * FDIM + r0 + tx] = __uint_as_float(tf32u(t[tx][ty + i]));
}

// ---------------------------------------------------------------------------
// L4: grouped GEMM1 — H = silu(X@w1) * (X@w3)
// 256 threads, 8 warps (2Mx4N), warp 64x32 both gates, BK=32, 3-stage cp.async.
// Inner loop: preload ALL fragments, then 32-MMA burst.
// ---------------------------------------------------------------------------
__global__ void __launch_bounds__(256, 1)
gemm1_kernel() {
    if (blockIdx.x >= g_nmt) return;
    extern __shared__ char smem[];
    const uint32_t sb = smem_u32(smem);
    const int tid = threadIdx.x, wid = tid >> 5, lane = tid & 31;
    const int wm = wid >> 2, wn = wid & 3;
    const int r4 = lane >> 2, c4 = lane & 3;
    const uint32_t xa = (uint32_t)((r4 & 6) << 3);

    const int e  = g_tile_e[blockIdx.x];
    const int r0 = g_tile_r[blockIdx.x];
    const int n0 = blockIdx.y * BN;

    int* s_tok = (int*)smem;
    if (tid < 128) {
        int t = g_row_token[r0 + tid];
        s_tok[tid] = ((unsigned)t < T_TOKENS) ? t : 0;
    }
    __syncthreads();

    const float* w1e = g_w1t + (size_t)e * FDIM * DDIM + (size_t)n0 * DDIM;
    const float* w3e = g_w3t + (size_t)e * FDIM * DDIM + (size_t)n0 * DDIM;

    const char* srcA[4]; const char* srcB1[4]; const char* srcB3[4];
    uint32_t dOf[4];
#pragma unroll
    for (int i = 0; i < 4; i++) {
        int idx = tid + i * 256;
        int row = idx >> 3, c = idx & 7;
        dOf[i] = (uint32_t)((c >> 2) * 8192 + row * 64 + (((c & 3) * 16) ^ ((row & 6) << 3)));
        srcA[i]  = (const char*)(g_xt + (size_t)s_tok[row] * DDIM + c * 4);
        srcB1[i] = (const char*)(w1e + (size_t)row * DDIM + c * 4);
        srcB3[i] = (const char*)(w3e + (size_t)row * DDIM + c * 4);
    }

    float accU[4][4][4], accV[4][4][4];
#pragma unroll
    for (int i = 0; i < 4; i++)
#pragma unroll
        for (int j = 0; j < 4; j++)
#pragma unroll
            for (int q = 0; q < 4; q++) { accU[i][j][q] = 0.f; accV[i][j][q] = 0.f; }

    const int KS = DDIM / BK;   // 32

#define G1_ISSUE(s)                                                            \
    do {                                                                       \
        uint32_t base_ = sb + 1024 + ((s) % 3) * STAGE1_SZ;                    \
        size_t off_ = (size_t)(s) * 128;                                       \
        _Pragma("unroll")                                                      \
        for (int i_ = 0; i_ < 4; i_++) {                                       \
            CP_ASYNC16(base_ + dOf[i_],         srcA[i_]  + off_);             \
            CP_ASYNC16(base_ + 16384 + dOf[i_], srcB1[i_] + off_);             \
            CP_ASYNC16(base_ + 32768 + dOf[i_], srcB3[i_] + off_);             \
        }                                                                      \
    } while (0)

    G1_ISSUE(0); CP_COMMIT();
    G1_ISSUE(1); CP_COMMIT();

    for (int ks = 0; ks < KS; ks++) {
        CP_WAIT1();
        __syncthreads();
        if (ks + 2 < KS) G1_ISSUE(ks + 2);
        CP_COMMIT();

        const uint32_t st = sb + 1024 + (ks % 3) * STAGE1_SZ;
#pragma unroll
        for (int k8 = 0; k8 < 4; k8++) {
            const uint32_t sub = (uint32_t)((k8 >> 1) * 8192);
            const uint32_t sA  = st + sub;
            const uint32_t sB1 = st + 16384 + sub;
            const uint32_t sB3 = st + 32768 + sub;
            const uint32_t k0 = (uint32_t)((((k8 & 1) * 8) + c4) * 4);
            const uint32_t k1 = k0 + 16;
            // --- preload ALL fragments ---
            uint32_t a[4][4], b1f[4][2], b3f[4][2];
#pragma unroll
            for (int mt = 0; mt < 4; mt++) {
                uint32_t rowb = sA + (uint32_t)((wm * 64 + mt * 16 + r4) * 64);
                a[mt][0] = lds32(rowb + (k0 ^ xa));
                a[mt][1] = lds32(rowb + 512 + (k0 ^ xa));
                a[mt][2] = lds32(rowb + (k1 ^ xa));
                a[mt][3] = lds32(rowb + 512 + (k1 ^ xa));
            }
#pragma unroll
            for (int nt = 0; nt < 4; nt++) {
                uint32_t nrow = (uint32_t)((wn * 32 + nt * 8 + r4) * 64);
                b1f[nt][0] = lds32(sB1 + nrow + (k0 ^ xa));
                b1f[nt][1] = lds32(sB1 + nrow + (k1 ^ xa));
                b3f[nt][0] = lds32(sB3 + nrow + (k0 ^ xa));
                b3f[nt][1] = lds32(sB3 + nrow + (k1 ^ xa));
            }
            // --- MMA burst ---
#pragma unroll
            for (int nt = 0; nt < 4; nt++)
#pragma unroll
                for (int mt = 0; mt < 4; mt++) {
                    mma8(accU[mt][nt], a[mt], b1f[nt][0], b1f[nt][1]);
                    mma8(accV[mt][nt], a[mt], b3f[nt][0], b3f[nt][1]);
                }
        }
    }

    // epilogue: h = silu(u)*v, tf32-rounded, write g_H
#pragma unroll
    for (int mt = 0; mt < 4; mt++) {
#pragma unroll
        for (int nt = 0; nt < 4; nt++) {
#pragma unroll
            for (int half = 0; half < 2; half++) {
                int r = r0 + wm * 64 + mt * 16 + r4 + half * 8;
                int cgl = n0 + wn * 32 + nt * 8 + 2 * c4;
                float u0 = accU[mt][nt][2 * half],     v0 = accV[mt][nt][2 * half];
                float u1 = accU[mt][nt][2 * half + 1], v1 = accV[mt][nt][2 * half + 1];
                float2 o;
                o.x = __uint_as_float(tf32u(u0 / (1.f + __expf(-u0)) * v0));
                o.y = __uint_as_float(tf32u(u1 / (1.f + __expf(-u1)) * v1));
                *(float2*)(g_H + (size_t)r * FDIM + cgl) = o;
            }
        }
    }
}

// ---------------------------------------------------------------------------
// L6: grouped GEMM2 — Y = H @ w2  (256 threads, 2Mx4N warps, warp 64x32, occ 2)
// ---------------------------------------------------------------------------
__global__ void __launch_bounds__(256, 2)
gemm2_kernel() {
    if (blockIdx.x >= g_nmt) return;
    extern __shared__ char smem[];
    const uint32_t sb = smem_u32(smem);
    const int tid = threadIdx.x, wid = tid >> 5, lane = tid & 31;
    const int wm = wid >> 2, wn = wid & 3;
    const int r4 = lane >> 2, c4 = lane & 3;
    const uint32_t xa = (uint32_t)((r4 & 6) << 3);

    const int e  = g_tile_e[blockIdx.x];
    const int r0 = g_tile_r[blockIdx.x];
    const int n0 = blockIdx.y * BN;

    const float* w2e = g_w2t + (size_t)e * DDIM * FDIM + (size_t)n0 * FDIM;

    const char* srcA[4]; const char* srcB[4];
    uint32_t dOf[4];
#pragma unroll
    for (int i = 0; i < 4; i++) {
        int idx = tid + i * 256;
        int row = idx >> 3, c = idx & 7;
        dOf[i] = (uint32_t)((c >> 2) * 8192 + row * 64 + (((c & 3) * 16) ^ ((row & 6) << 3)));
        srcA[i] = (const char*)(g_H + (size_t)(r0 + row) * FDIM + c * 4);
        srcB[i] = (const char*)(w2e + (size_t)row * FDIM + c * 4);
    }

    float acc[4][4][4];
#pragma unroll
    for (int i = 0; i < 4; i++)
#pragma unroll
        for (int j = 0; j < 4; j++)
#pragma unroll
            for (int q = 0; q < 4; q++) acc[i][j][q] = 0.f;

    const int KS = FDIM / BK;   // 128

#define G2_ISSUE(s)                                                            \
    do {                                                                       \
        uint32_t base_ = sb + 1024 + ((s) % 3) * STAGE2_SZ;                    \
        size_t off_ = (size_t)(s) * 128;                                       \
        _Pragma("unroll")                                                      \
        for (int i_ = 0; i_ < 4; i_++) {                                       \
            CP_ASYNC16(base_ + dOf[i_],         srcA[i_] + off_);              \
            CP_ASYNC16(base_ + 16384 + dOf[i_], srcB[i_] + off_);              \
        }                                                                      \
    } while (0)

    G2_ISSUE(0); CP_COMMIT();
    G2_ISSUE(1); CP_COMMIT();

    for (int ks = 0; ks < KS; ks++) {
        CP_WAIT1();
        __syncthreads();
        if (ks + 2 < KS) G2_ISSUE(ks + 2);
        CP_COMMIT();

        const uint32_t st = sb + 1024 + (ks % 3) * STAGE2_SZ;
#pragma unroll
        for (int k8 = 0; k8 < 4; k8++) {
            const uint32_t sub = (uint32_t)((k8 >> 1) * 8192);
            const uint32_t sA = st + sub;
            const uint32_t sB = st + 16384 + sub;
            const uint32_t k0 = (uint32_t)((((k8 & 1) * 8) + c4) * 4);
            const uint32_t k1 = k0 + 16;
            uint32_t a[4][4], bf[4][2];
#pragma unroll
            for (int mt = 0; mt < 4; mt++) {
                uint32_t rowb = sA + (uint32_t)((wm * 64 + mt * 16 + r4) * 64);
                a[mt][0] = lds32(rowb + (k0 ^ xa));
                a[mt][1] = lds32(rowb + 512 + (k0 ^ xa));
                a[mt][2] = lds32(rowb + (k1 ^ xa));
                a[mt][3] = lds32(rowb + 512 + (k1 ^ xa));
            }
#pragma unroll
            for (int nt = 0; nt < 4; nt++) {
                uint32_t nrow = (uint32_t)((wn * 32 + nt * 8 + r4) * 64);
                bf[nt][0] = lds32(sB + nrow + (k0 ^ xa));
                bf[nt][1] = lds32(sB + nrow + (k1 ^ xa));
            }
#pragma unroll
            for (int nt = 0; nt < 4; nt++)
#pragma unroll
                for (int mt = 0; mt < 4; mt++)
                    mma8(acc[mt][nt], a[mt], bf[nt][0], bf[nt][1]);
        }
    }

#pragma unroll
    for (int mt = 0; mt < 4; mt++) {
#pragma unroll
        for (int nt = 0; nt < 4; nt++) {
#pragma unroll
            for (int half = 0; half < 2; half++) {
                int r = r0 + wm * 64 + mt * 16 + r4 + half * 8;
                int cgl = n0 + wn * 32 + nt * 8 + 2 * c4;
                float2 o;
                o.x = acc[mt][nt][2 * half];
                o.y = acc[mt][nt][2 * half + 1];
                *(float2*)(g_Y + (size_t)r * DDIM + cgl) = o;
            }
        }
    }
}

// ---------------------------------------------------------------------------
// L7: combine
// ---------------------------------------------------------------------------
__global__ void combine_kernel(float* __restrict__ out) {
    int t = blockIdx.x;
    int d = threadIdx.x * 4;
    float w0 = g_tok_w[2 * t], w1v = g_tok_w[2 * t + 1];
    int   r0 = g_tok_row[2 * t], r1 = g_tok_row[2 * t + 1];
    const float4 a = *(const float4*)(g_Y + (size_t)r0 * DDIM + d);
    const float4 b = *(const float4*)(g_Y + (size_t)r1 * DDIM + d);
    float4 o;
    o.x = w0 * a.x + w1v * b.x;
    o.y = w0 * a.y + w1v * b.y;
    o.z = w0 * a.z + w1v * b.z;
    o.w = w0 * a.w + w1v * b.w;
    *(float4*)(out + (size_t)t * DDIM + d) = o;
}

// ---------------------------------------------------------------------------
// Launcher — fork/join stream overlap; gemm1 is the 4th submitted kernel
// ---------------------------------------------------------------------------
extern "C" void kernel_launch(void* const* d_in, const int* in_sizes, int n_in,
                              void* d_out, int out_size) {
    const float* x  = (const float*)d_in[0];
    const float* rw = (const float*)d_in[1];
    const float* rb = (const float*)d_in[2];
    const float* w1 = (const float*)d_in[3];
    const float* w2 = (const float*)d_in[4];
    const float* w3 = (const float*)d_in[5];
    float* out = (float*)d_out;

    cudaFuncSetAttribute(gemm1_kernel, cudaFuncAttributeMaxDynamicSharedMemorySize, SMEM1_SZ);
    cudaFuncSetAttribute(gemm2_kernel, cudaFuncAttributeMaxDynamicSharedMemorySize, SMEM2_SZ);

    float *w1t, *w3t, *w2t;
    cudaGetSymbolAddress((void**)&w1t, g_w1t);
    cudaGetSymbolAddress((void**)&w3t, g_w3t);
    cudaGetSymbolAddress((void**)&w2t, g_w2t);

    cudaStream_t s1;
    cudaEvent_t e0, e13, e2;
    cudaStreamCreateWithFlags(&s1, cudaStreamNonBlocking);
    cudaEventCreateWithFlags(&e0, cudaEventDisableTiming);
    cudaEventCreateWithFlags(&e13, cudaEventDisableTiming);
    cudaEventCreateWithFlags(&e2, cudaEventDisableTiming);

    // fork s1 from the main (capture-origin) stream
    cudaEventRecord(e0, 0);
    cudaStreamWaitEvent(s1, e0, 0);

    convx_init_kernel<<<(T_TOKENS * DDIM / 4) / 256, 256>>>(x);              // #1 main
    router_fused_kernel<<<64, 256>>>(x, rw, rb);                             // #2 main
    transpose13_kernel<<<dim3(FDIM / 32, DDIM / 32, 2 * NEXP), dim3(32, 8), 0, s1>>>(
        w1, w3, w1t, w3t);                                                   // #3 s1
    cudaEventRecord(e13, s1);
    cudaStreamWaitEvent(0, e13, 0);
    gemm1_kernel<<<dim3(MAX_MT, FDIM / BN), 256, SMEM1_SZ>>>();              // #4 main
    transpose2_kernel<<<dim3(DDIM / 32, FDIM / 32, NEXP), dim3(32, 8), 0, s1>>>(
        w2, w2t);                                                            // #5 s1 (|| gemm1)
    cudaEventRecord(e2, s1);
    cudaStreamWaitEvent(0, e2, 0);                                           // join s1
    gemm2_kernel<<<dim3(MAX_MT, DDIM / BN), 256, SMEM2_SZ>>>();              // #6 main
    combine_kernel<<<T_TOKENS, 256>>>(out);                                  // #7 main
}

// round 8
// speedup vs baseline: 1.7642x; 1.6090x over previous
#include <cuda_runtime.h>
#include <cuda_fp16.h>
#include <cstdint>

// ---------------------------------------------------------------------------
// Problem constants
// ---------------------------------------------------------------------------
#define T_TOKENS 4096
#define DDIM 1024
#define FDIM 4096
#define NEXP 8
#define BM 128
#define BN 128
#define BK 32
#define MAX_MT 72
#define ROWS_CAP (MAX_MT * 128)

// ---------------------------------------------------------------------------
// Device scratch (fp16 operands, fp32 outputs)
// ---------------------------------------------------------------------------
__device__ int    g_cnt[NEXP];
__device__ int    g_cur[NEXP];
__device__ int    g_done;
__device__ int    g_nmt;
__device__ int    g_tile_e[MAX_MT];
__device__ int    g_tile_r[MAX_MT];
__device__ int    g_row_token[ROWS_CAP];
__device__ int    g_tok_e[T_TOKENS * 2];
__device__ int    g_tok_row[T_TOKENS * 2];
__device__ float  g_tok_w[T_TOKENS * 2];
__device__ __half g_H[(size_t)ROWS_CAP * FDIM];
__device__ float  g_Y[(size_t)ROWS_CAP * DDIM];
__device__ __half g_xt[(size_t)T_TOKENS * DDIM];
__device__ __half g_w1t[(size_t)NEXP * DDIM * FDIM];
__device__ __half g_w3t[(size_t)NEXP * DDIM * FDIM];
__device__ __half g_w2t[(size_t)NEXP * DDIM * FDIM];

// ---------------------------------------------------------------------------
// Helpers
// ---------------------------------------------------------------------------
__device__ __forceinline__ uint32_t smem_u32(const void* p) {
    uint32_t a;
    asm("{ .reg .u64 t; cvta.to.shared.u64 t, %1; cvt.u32.u64 %0, t; }" : "=r"(a) : "l"(p));
    return a;
}
__device__ __forceinline__ uint32_t lds32(uint32_t a) {
    uint32_t v;
    asm volatile("ld.shared.b32 %0, [%1];" : "=r"(v) : "r"(a));
    return v;
}
__device__ __forceinline__ uint32_t h2u(__half2 h) {
    uint32_t u;
    __builtin_memcpy(&u, &h, 4);
    return u;
}
// m16n8k16 fp16 MMA, fp32 accumulate (base ISA, accepted on plain sm_103)
__device__ __forceinline__ void mma16(float* d, const uint32_t* a, uint32_t b0, uint32_t b1) {
    asm volatile(
        "mma.sync.aligned.m16n8k16.row.col.f32.f16.f16.f32 "
        "{%0,%1,%2,%3}, {%4,%5,%6,%7}, {%8,%9}, {%0,%1,%2,%3};"
        : "+f"(d[0]), "+f"(d[1]), "+f"(d[2]), "+f"(d[3])
        : "r"(a[0]), "r"(a[1]), "r"(a[2]), "r"(a[3]), "r"(b0), "r"(b1));
}
#define CP_ASYNC16(dst, src) \
    asm volatile("cp.async.cg.shared.global [%0], [%1], 16;" :: "r"(dst), "l"(src))
#define CP_COMMIT() asm volatile("cp.async.commit_group;" ::: "memory")
#define CP_WAIT1()  asm volatile("cp.async.wait_group 1;" ::: "memory")

// Region: 128 rows x 32 fp16 = 64B rows, SW64 swizzle, 8KB per region.
// Staged chunk c (16B) of row r: r*64 + ((c*16) ^ ((r&6)<<3)).
// Fragment load (k-pair at byte b in row r): r*64 + (b ^ ((r&6)<<3)).
// Conflict-free for all k-groups (re-verified for kb=0 and kb=32).
#define STAGE1_SZ 24576   // A + B1 + B3 (3 x 8KB)
#define STAGE2_SZ 16384   // A + B
#define SMEM1_SZ (1024 + 3 * STAGE1_SZ)
#define SMEM2_SZ (1024 + 3 * STAGE2_SZ)

// ---------------------------------------------------------------------------
// L1: convx + init — x -> fp16
// ---------------------------------------------------------------------------
__global__ void convx_init_kernel(const float* __restrict__ x) {
    int i = blockIdx.x * blockDim.x + threadIdx.x;   // 8 elems/thread
    if (blockIdx.x == 0) {
        if (threadIdx.x < NEXP) g_cnt[threadIdx.x] = 0;
        if (threadIdx.x == NEXP) g_done = 0;
    }
    const float4 v0 = ((const float4*)x)[2 * i];
    const float4 v1 = ((const float4*)x)[2 * i + 1];
    uint4 o;
    o.x = h2u(__floats2half2_rn(v0.x, v0.y));
    o.y = h2u(__floats2half2_rn(v0.z, v0.w));
    o.z = h2u(__floats2half2_rn(v1.x, v1.y));
    o.w = h2u(__floats2half2_rn(v1.z, v1.w));
    ((uint4*)g_xt)[i] = o;
}

// ---------------------------------------------------------------------------
// L2: fused router + scan + scatter (last-CTA pattern); 64 CTAs
// ---------------------------------------------------------------------------
__global__ void __launch_bounds__(256)
router_fused_kernel(const float* __restrict__ x, const float* __restrict__ rw,
                    const float* __restrict__ rb) {
    __shared__ float s_rw[NEXP * DDIM];
    __shared__ int s_last;
    const int tid = threadIdx.x, wid = tid >> 5, lane = tid & 31;

    for (int i = tid; i < NEXP * DDIM / 2; i += 256)
        ((float2*)s_rw)[i] = ((const float2*)rw)[i];
    __syncthreads();

    const int tbase = blockIdx.x * 64 + wid * 8;
    for (int j = 0; j < 8; j++) {
        const int t = tbase + j;
        const float* xt = x + (size_t)t * DDIM;
        float acc[NEXP];
#pragma unroll
        for (int e = 0; e < NEXP; e++) acc[e] = 0.f;
        for (int i = lane; i < DDIM; i += 32) {
            float xv = xt[i];
#pragma unroll
            for (int e = 0; e < NEXP; e++) acc[e] += xv * s_rw[e * DDIM + i];
        }
#pragma unroll
        for (int off = 16; off; off >>= 1)
#pragma unroll
            for (int e = 0; e < NEXP; e++) acc[e] += __shfl_xor_sync(0xffffffffu, acc[e], off);
        if (lane == 0) {
#pragma unroll
            for (int e = 0; e < NEXP; e++) acc[e] += rb[e];
            int e0 = 0; float l0 = acc[0];
#pragma unroll
            for (int e = 1; e < NEXP; e++) if (acc[e] > l0) { l0 = acc[e]; e0 = e; }
            int e1 = (e0 == 0) ? 1 : 0; float l1 = acc[e1];
#pragma unroll
            for (int e = 0; e < NEXP; e++)
                if (e != e0 && acc[e] > l1) { l1 = acc[e]; e1 = e; }
            float w0 = 1.f / (1.f + __expf(l1 - l0));
            g_tok_e[2 * t] = e0;  g_tok_e[2 * t + 1] = e1;
            g_tok_w[2 * t] = w0;  g_tok_w[2 * t + 1] = 1.f - w0;
            atomicAdd(&g_cnt[e0], 1);
            atomicAdd(&g_cnt[e1], 1);
        }
    }

    __syncthreads();
    if (tid == 0) {
        __threadfence();
        int v = atomicAdd(&g_done, 1);
        s_last = (v == (int)gridDim.x - 1);
    }
    __syncthreads();
    if (!s_last) return;
    __threadfence();

    if (tid == 0) {
        int base = 0, nt = 0;
        for (int e = 0; e < NEXP; e++) {
            g_cur[e] = base;
            int tiles = (g_cnt[e] + 127) >> 7;
            for (int i = 0; i < tiles; i++) { g_tile_e[nt] = e; g_tile_r[nt] = base + i * 128; nt++; }
            base += tiles << 7;
        }
        g_nmt = nt;
        g_done = 0;
    }
    __syncthreads();

    for (int t = tid; t < T_TOKENS; t += 256) {
#pragma unroll
        for (int k = 0; k < 2; k++) {
            int e = g_tok_e[2 * t + k];
            int r = atomicAdd(&g_cur[e], 1);
            g_row_token[r] = t;
            g_tok_row[2 * t + k] = r;
        }
    }
}

// ---------------------------------------------------------------------------
// Weight transposes (+fp16 convert) — forked stream
// ---------------------------------------------------------------------------
__global__ void transpose13_kernel(const float* __restrict__ w1, const float* __restrict__ w3,
                                   __half* __restrict__ w1t, __half* __restrict__ w3t) {
    __shared__ float t[32][33];
    const int zz = blockIdx.z;
    const float* src = (zz < NEXP) ? w1 : w3;
    __half* dst = (zz < NEXP) ? w1t : w3t;
    const size_t mo = (size_t)(zz & 7) * DDIM * FDIM;
    const int c0 = blockIdx.x * 32, r0 = blockIdx.y * 32;
    const int tx = threadIdx.x, ty = threadIdx.y;
#pragma unroll
    for (int i = 0; i < 32; i += 8)
        t[ty + i][tx] = src[mo + (size_t)(r0 + ty + i) * FDIM + c0 + tx];
    __syncthreads();
#pragma unroll
    for (int i = 0; i < 32; i += 8)
        dst[mo + (size_t)(c0 + ty + i) * DDIM + r0 + tx] = __float2half_rn(t[tx][ty + i]);
}

__global__ void transpose2_kernel(const float* __restrict__ src, __half* __restrict__ dst) {
    __shared__ float t[32][33];
    const size_t mo = (size_t)blockIdx.z * DDIM * FDIM;
    const int c0 = blockIdx.x * 32, r0 = blockIdx.y * 32;
    const int tx = threadIdx.x, ty = threadIdx.y;
#pragma unroll
    for (int i = 0; i < 32; i += 8)
        t[ty + i][tx] = src[mo + (size_t)(r0 + ty + i) * DDIM + c0 + tx];
    __syncthreads();
#pragma unroll
    for (int i = 0; i < 32; i += 8)
        dst[mo + (size_t)(c0 + ty + i) * FDIM + r0 + tx] = __float2half_rn(t[tx][ty + i]);
}

// ---------------------------------------------------------------------------
// L4: grouped GEMM1 — H = silu(X@w1) * (X@w3)   [fp16 MMA]
// 256 threads, 8 warps (2Mx4N), warp 64x32 both gates, BK=32, 3-stage cp.async.
// ---------------------------------------------------------------------------
__global__ void __launch_bounds__(256, 1)
gemm1_kernel() {
    if (blockIdx.x >= g_nmt) return;
    extern __shared__ char smem[];
    const uint32_t sb = smem_u32(smem);
    const int tid = threadIdx.x, wid = tid >> 5, lane = tid & 31;
    const int wm = wid >> 2, wn = wid & 3;
    const int r4 = lane >> 2, c4 = lane & 3;
    const uint32_t xa = (uint32_t)((r4 & 6) << 3);

    const int e  = g_tile_e[blockIdx.x];
    const int r0 = g_tile_r[blockIdx.x];
    const int n0 = blockIdx.y * BN;

    int* s_tok = (int*)smem;
    if (tid < 128) {
        int t = g_row_token[r0 + tid];
        s_tok[tid] = ((unsigned)t < T_TOKENS) ? t : 0;
    }
    __syncthreads();

    const __half* w1e = g_w1t + (size_t)e * FDIM * DDIM + (size_t)n0 * DDIM;
    const __half* w3e = g_w3t + (size_t)e * FDIM * DDIM + (size_t)n0 * DDIM;

    // staging: 512 chunks per 8KB region, 2 per thread
    const char* srcA[2]; const char* srcB1[2]; const char* srcB3[2];
    uint32_t dOf[2];
#pragma unroll
    for (int i = 0; i < 2; i++) {
        int idx = tid + i * 256;
        int row = idx >> 2, c = idx & 3;
        dOf[i] = (uint32_t)(row * 64 + ((c * 16) ^ ((row & 6) << 3)));
        srcA[i]  = (const char*)(g_xt + (size_t)s_tok[row] * DDIM + c * 8);
        srcB1[i] = (const char*)(w1e + (size_t)row * DDIM + c * 8);
        srcB3[i] = (const char*)(w3e + (size_t)row * DDIM + c * 8);
    }

    float accU[4][4][4], accV[4][4][4];
#pragma unroll
    for (int i = 0; i < 4; i++)
#pragma unroll
        for (int j = 0; j < 4; j++)
#pragma unroll
            for (int q = 0; q < 4; q++) { accU[i][j][q] = 0.f; accV[i][j][q] = 0.f; }

    const int KS = DDIM / BK;   // 32

#define G1_ISSUE(s)                                                            \
    do {                                                                       \
        uint32_t base_ = sb + 1024 + ((s) % 3) * STAGE1_SZ;                    \
        size_t off_ = (size_t)(s) * 64;                                        \
        _Pragma("unroll")                                                      \
        for (int i_ = 0; i_ < 2; i_++) {                                       \
            CP_ASYNC16(base_ + dOf[i_],         srcA[i_]  + off_);             \
            CP_ASYNC16(base_ + 8192  + dOf[i_], srcB1[i_] + off_);             \
            CP_ASYNC16(base_ + 16384 + dOf[i_], srcB3[i_] + off_);             \
        }                                                                      \
    } while (0)

    G1_ISSUE(0); CP_COMMIT();
    G1_ISSUE(1); CP_COMMIT();

    for (int ks = 0; ks < KS; ks++) {
        CP_WAIT1();
        __syncthreads();
        if (ks + 2 < KS) G1_ISSUE(ks + 2);
        CP_COMMIT();

        const uint32_t sA  = sb + 1024 + (ks % 3) * STAGE1_SZ;
        const uint32_t sB1 = sA + 8192;
        const uint32_t sB3 = sA + 16384;
#pragma unroll
        for (int g = 0; g < 2; g++) {           // two k16 groups per BK=32
            const uint32_t k0 = (uint32_t)((g * 32 + 4 * c4) ^ xa);
            const uint32_t k1 = (uint32_t)((g * 32 + 4 * c4 + 16) ^ xa);
            uint32_t a[4][4], b1f[4][2], b3f[4][2];
#pragma unroll
            for (int mt = 0; mt < 4; mt++) {
                uint32_t rowb = sA + (uint32_t)((wm * 64 + mt * 16 + r4) * 64);
                a[mt][0] = lds32(rowb + k0);
                a[mt][1] = lds32(rowb + 512 + k0);
                a[mt][2] = lds32(rowb + k1);
                a[mt][3] = lds32(rowb + 512 + k1);
            }
#pragma unroll
            for (int nt = 0; nt < 4; nt++) {
                uint32_t nrow = (uint32_t)((wn * 32 + nt * 8 + r4) * 64);
                b1f[nt][0] = lds32(sB1 + nrow + k0);
                b1f[nt][1] = lds32(sB1 + nrow + k1);
                b3f[nt][0] = lds32(sB3 + nrow + k0);
                b3f[nt][1] = lds32(sB3 + nrow + k1);
            }
#pragma unroll
            for (int nt = 0; nt < 4; nt++)
#pragma unroll
                for (int mt = 0; mt < 4; mt++) {
                    mma16(accU[mt][nt], a[mt], b1f[nt][0], b1f[nt][1]);
                    mma16(accV[mt][nt], a[mt], b3f[nt][0], b3f[nt][1]);
                }
        }
    }

    // epilogue: h = silu(u)*v -> fp16 H
#pragma unroll
    for (int mt = 0; mt < 4; mt++) {
#pragma unroll
        for (int nt = 0; nt < 4; nt++) {
#pragma unroll
            for (int half = 0; half < 2; half++) {
                int r = r0 + wm * 64 + mt * 16 + r4 + half * 8;
                int cgl = n0 + wn * 32 + nt * 8 + 2 * c4;
                float u0 = accU[mt][nt][2 * half],     v0 = accV[mt][nt][2 * half];
                float u1 = accU[mt][nt][2 * half + 1], v1 = accV[mt][nt][2 * half + 1];
                __half2 o = __floats2half2_rn(u0 / (1.f + __expf(-u0)) * v0,
                                              u1 / (1.f + __expf(-u1)) * v1);
                *(__half2*)(g_H + (size_t)r * FDIM + cgl) = o;
            }
        }
    }
}

// ---------------------------------------------------------------------------
// L6: grouped GEMM2 — Y = H @ w2   [fp16 MMA]
// ---------------------------------------------------------------------------
__global__ void __launch_bounds__(256, 2)
gemm2_kernel() {
    if (blockIdx.x >= g_nmt) return;
    extern __shared__ char smem[];
    const uint32_t sb = smem_u32(smem);
    const int tid = threadIdx.x, wid = tid >> 5, lane = tid & 31;
    const int wm = wid >> 2, wn = wid & 3;
    const int r4 = lane >> 2, c4 = lane & 3;
    const uint32_t xa = (uint32_t)((r4 & 6) << 3);

    const int e  = g_tile_e[blockIdx.x];
    const int r0 = g_tile_r[blockIdx.x];
    const int n0 = blockIdx.y * BN;

    const __half* w2e = g_w2t + (size_t)e * DDIM * FDIM + (size_t)n0 * FDIM;

    const char* srcA[2]; const char* srcB[2];
    uint32_t dOf[2];
#pragma unroll
    for (int i = 0; i < 2; i++) {
        int idx = tid + i * 256;
        int row = idx >> 2, c = idx & 3;
        dOf[i] = (uint32_t)(row * 64 + ((c * 16) ^ ((row & 6) << 3)));
        srcA[i] = (const char*)(g_H + (size_t)(r0 + row) * FDIM + c * 8);
        srcB[i] = (const char*)(w2e + (size_t)row * FDIM + c * 8);
    }

    float acc[4][4][4];
#pragma unroll
    for (int i = 0; i < 4; i++)
#pragma unroll
        for (int j = 0; j < 4; j++)
#pragma unroll
            for (int q = 0; q < 4; q++) acc[i][j][q] = 0.f;

    const int KS = FDIM / BK;   // 128

#define G2_ISSUE(s)                                                            \
    do {                                                                       \
        uint32_t base_ = sb + 1024 + ((s) % 3) * STAGE2_SZ;                    \
        size_t off_ = (size_t)(s) * 64;                                        \
        _Pragma("unroll")                                                      \
        for (int i_ = 0; i_ < 2; i_++) {                                       \
            CP_ASYNC16(base_ + dOf[i_],        srcA[i_] + off_);               \
            CP_ASYNC16(base_ + 8192 + dOf[i_], srcB[i_] + off_);               \
        }                                                                      \
    } while (0)

    G2_ISSUE(0); CP_COMMIT();
    G2_ISSUE(1); CP_COMMIT();

    for (int ks = 0; ks < KS; ks++) {
        CP_WAIT1();
        __syncthreads();
        if (ks + 2 < KS) G2_ISSUE(ks + 2);
        CP_COMMIT();

        const uint32_t sA = sb + 1024 + (ks % 3) * STAGE2_SZ;
        const uint32_t sB = sA + 8192;
#pragma unroll
        for (int g = 0; g < 2; g++) {
            const uint32_t k0 = (uint32_t)((g * 32 + 4 * c4) ^ xa);
            const uint32_t k1 = (uint32_t)((g * 32 + 4 * c4 + 16) ^ xa);
            uint32_t a[4][4], bf[4][2];
#pragma unroll
            for (int mt = 0; mt < 4; mt++) {
                uint32_t rowb = sA + (uint32_t)((wm * 64 + mt * 16 + r4) * 64);
                a[mt][0] = lds32(rowb + k0);
                a[mt][1] = lds32(rowb + 512 + k0);
                a[mt][2] = lds32(rowb + k1);
                a[mt][3] = lds32(rowb + 512 + k1);
            }
#pragma unroll
            for (int nt = 0; nt < 4; nt++) {
                uint32_t nrow = (uint32_t)((wn * 32 + nt * 8 + r4) * 64);
                bf[nt][0] = lds32(sB + nrow + k0);
                bf[nt][1] = lds32(sB + nrow + k1);
            }
#pragma unroll
            for (int nt = 0; nt < 4; nt++)
#pragma unroll
                for (int mt = 0; mt < 4; mt++)
                    mma16(acc[mt][nt], a[mt], bf[nt][0], bf[nt][1]);
        }
    }

#pragma unroll
    for (int mt = 0; mt < 4; mt++) {
#pragma unroll
        for (int nt = 0; nt < 4; nt++) {
#pragma unroll
            for (int half = 0; half < 2; half++) {
                int r = r0 + wm * 64 + mt * 16 + r4 + half * 8;
                int cgl = n0 + wn * 32 + nt * 8 + 2 * c4;
                float2 o;
                o.x = acc[mt][nt][2 * half];
                o.y = acc[mt][nt][2 * half + 1];
                *(float2*)(g_Y + (size_t)r * DDIM + cgl) = o;
            }
        }
    }
}

// ---------------------------------------------------------------------------
// L7: combine
// ---------------------------------------------------------------------------
__global__ void combine_kernel(float* __restrict__ out) {
    int t = blockIdx.x;
    int d = threadIdx.x * 4;
    float w0 = g_tok_w[2 * t], w1v = g_tok_w[2 * t + 1];
    int   r0 = g_tok_row[2 * t], r1 = g_tok_row[2 * t + 1];
    const float4 a = *(const float4*)(g_Y + (size_t)r0 * DDIM + d);
    const float4 b = *(const float4*)(g_Y + (size_t)r1 * DDIM + d);
    float4 o;
    o.x = w0 * a.x + w1v * b.x;
    o.y = w0 * a.y + w1v * b.y;
    o.z = w0 * a.z + w1v * b.z;
    o.w = w0 * a.w + w1v * b.w;
    *(float4*)(out + (size_t)t * DDIM + d) = o;
}

// ---------------------------------------------------------------------------
// Launcher — fork/join overlap; gemm1 is the 4th submitted kernel
// ---------------------------------------------------------------------------
extern "C" void kernel_launch(void* const* d_in, const int* in_sizes, int n_in,
                              void* d_out, int out_size) {
    const float* x  = (const float*)d_in[0];
    const float* rw = (const float*)d_in[1];
    const float* rb = (const float*)d_in[2];
    const float* w1 = (const float*)d_in[3];
    const float* w2 = (const float*)d_in[4];
    const float* w3 = (const float*)d_in[5];
    float* out = (float*)d_out;

    cudaFuncSetAttribute(gemm1_kernel, cudaFuncAttributeMaxDynamicSharedMemorySize, SMEM1_SZ);
    cudaFuncSetAttribute(gemm2_kernel, cudaFuncAttributeMaxDynamicSharedMemorySize, SMEM2_SZ);

    __half *w1t, *w3t, *w2t;
    cudaGetSymbolAddress((void**)&w1t, g_w1t);
    cudaGetSymbolAddress((void**)&w3t, g_w3t);
    cudaGetSymbolAddress((void**)&w2t, g_w2t);

    cudaStream_t s1;
    cudaEvent_t e0, e13, e2;
    cudaStreamCreateWithFlags(&s1, cudaStreamNonBlocking);
    cudaEventCreateWithFlags(&e0, cudaEventDisableTiming);
    cudaEventCreateWithFlags(&e13, cudaEventDisableTiming);
    cudaEventCreateWithFlags(&e2, cudaEventDisableTiming);

    cudaEventRecord(e0, 0);
    cudaStreamWaitEvent(s1, e0, 0);

    convx_init_kernel<<<(T_TOKENS * DDIM / 8) / 256, 256>>>(x);              // #1 main
    router_fused_kernel<<<64, 256>>>(x, rw, rb);                             // #2 main
    transpose13_kernel<<<dim3(FDIM / 32, DDIM / 32, 2 * NEXP), dim3(32, 8), 0, s1>>>(
        w1, w3, w1t, w3t);                                                   // #3 s1
    cudaEventRecord(e13, s1);
    cudaStreamWaitEvent(0, e13, 0);
    gemm1_kernel<<<dim3(MAX_MT, FDIM / BN), 256, SMEM1_SZ>>>();              // #4 main
    transpose2_kernel<<<dim3(DDIM / 32, FDIM / 32, NEXP), dim3(32, 8), 0, s1>>>(
        w2, w2t);                                                            // #5 s1 (|| gemm1)
    cudaEventRecord(e2, s1);
    cudaStreamWaitEvent(0, e2, 0);
    gemm2_kernel<<<dim3(MAX_MT, DDIM / BN), 256, SMEM2_SZ>>>();              // #6 main
    combine_kernel<<<T_TOKENS, 256>>>(out);                                  // #7 main
}

// round 9
// speedup vs baseline: 2.0414x; 1.1572x over previous
#include <cuda_runtime.h>
#include <cuda_fp16.h>
#include <cstdint>

// ---------------------------------------------------------------------------
// Problem constants
// ---------------------------------------------------------------------------
#define T_TOKENS 4096
#define DDIM 1024
#define FDIM 4096
#define NEXP 8
#define BM 128
#define BN 128
#define BK 64
#define MAX_MT 72
#define ROWS_CAP (MAX_MT * 128)

// ---------------------------------------------------------------------------
// Device scratch (fp16 operands, fp32 outputs)
// ---------------------------------------------------------------------------
__device__ int    g_cnt[NEXP];
__device__ int    g_cur[NEXP];
__device__ int    g_done;
__device__ int    g_nmt;
__device__ int    g_tile_e[MAX_MT];
__device__ int    g_tile_r[MAX_MT];
__device__ int    g_row_token[ROWS_CAP];
__device__ int    g_tok_e[T_TOKENS * 2];
__device__ int    g_tok_row[T_TOKENS * 2];
__device__ float  g_tok_w[T_TOKENS * 2];
__device__ __half g_H[(size_t)ROWS_CAP * FDIM];
__device__ float  g_Y[(size_t)ROWS_CAP * DDIM];
__device__ __half g_xt[(size_t)T_TOKENS * DDIM];
__device__ __half g_w1t[(size_t)NEXP * DDIM * FDIM];
__device__ __half g_w3t[(size_t)NEXP * DDIM * FDIM];
__device__ __half g_w2t[(size_t)NEXP * DDIM * FDIM];

// ---------------------------------------------------------------------------
// Helpers
// ---------------------------------------------------------------------------
__device__ __forceinline__ uint32_t smem_u32(const void* p) {
    uint32_t a;
    asm("{ .reg .u64 t; cvta.to.shared.u64 t, %1; cvt.u32.u64 %0, t; }" : "=r"(a) : "l"(p));
    return a;
}
__device__ __forceinline__ uint32_t lds32(uint32_t a) {
    uint32_t v;
    asm volatile("ld.shared.b32 %0, [%1];" : "=r"(v) : "r"(a));
    return v;
}
__device__ __forceinline__ uint32_t h2u(__half2 h) {
    uint32_t u;
    __builtin_memcpy(&u, &h, 4);
    return u;
}
__device__ __forceinline__ void mma16(float* d, const uint32_t* a, uint32_t b0, uint32_t b1) {
    asm volatile(
        "mma.sync.aligned.m16n8k16.row.col.f32.f16.f16.f32 "
        "{%0,%1,%2,%3}, {%4,%5,%6,%7}, {%8,%9}, {%0,%1,%2,%3};"
        : "+f"(d[0]), "+f"(d[1]), "+f"(d[2]), "+f"(d[3])
        : "r"(a[0]), "r"(a[1]), "r"(a[2]), "r"(a[3]), "r"(b0), "r"(b1));
}
#define CP_ASYNC16(dst, src) \
    asm volatile("cp.async.cg.shared.global [%0], [%1], 16;" :: "r"(dst), "l"(src))
#define CP_COMMIT() asm volatile("cp.async.commit_group;" ::: "memory")
#define CP_WAIT1()  asm volatile("cp.async.wait_group 1;" ::: "memory")

// Region: 128 rows x 64 fp16 = 128B rows, SW128 swizzle, 16KB per region.
// Staged chunk c (16B) of row r : r*128 + ((c*16) ^ ((r&7)<<4))
// Fragment k-byte b of row r    : r*128 + (b ^ ((r&7)<<4))
// Conflict-free: bank bits 2-3 from c4, bits 4-6 = kbase ^ r (bijective over 8 rows).
#define REGION_SZ 16384
#define STAGE1_SZ 49152   // A + B1 + B3
#define STAGE2_SZ 32768   // A + B
#define SMEM1_SZ (1024 + 3 * STAGE1_SZ)
#define SMEM2_SZ (1024 + 3 * STAGE2_SZ)

// ---------------------------------------------------------------------------
// L1: convx + init — x -> fp16
// ---------------------------------------------------------------------------
__global__ void convx_init_kernel(const float* __restrict__ x) {
    int i = blockIdx.x * blockDim.x + threadIdx.x;   // 8 elems/thread
    if (blockIdx.x == 0) {
        if (threadIdx.x < NEXP) g_cnt[threadIdx.x] = 0;
        if (threadIdx.x == NEXP) g_done = 0;
    }
    const float4 v0 = ((const float4*)x)[2 * i];
    const float4 v1 = ((const float4*)x)[2 * i + 1];
    uint4 o;
    o.x = h2u(__floats2half2_rn(v0.x, v0.y));
    o.y = h2u(__floats2half2_rn(v0.z, v0.w));
    o.z = h2u(__floats2half2_rn(v1.x, v1.y));
    o.w = h2u(__floats2half2_rn(v1.z, v1.w));
    ((uint4*)g_xt)[i] = o;
}

// ---------------------------------------------------------------------------
// L2: fused router + scan + scatter (last-CTA pattern); 64 CTAs
// ---------------------------------------------------------------------------
__global__ void __launch_bounds__(256)
router_fused_kernel(const float* __restrict__ x, const float* __restrict__ rw,
                    const float* __restrict__ rb) {
    __shared__ float s_rw[NEXP * DDIM];
    __shared__ int s_last;
    const int tid = threadIdx.x, wid = tid >> 5, lane = tid & 31;

    for (int i = tid; i < NEXP * DDIM / 2; i += 256)
        ((float2*)s_rw)[i] = ((const float2*)rw)[i];
    __syncthreads();

    const int tbase = blockIdx.x * 64 + wid * 8;
    for (int j = 0; j < 8; j++) {
        const int t = tbase + j;
        const float* xt = x + (size_t)t * DDIM;
        float acc[NEXP];
#pragma unroll
        for (int e = 0; e < NEXP; e++) acc[e] = 0.f;
        for (int i = lane; i < DDIM; i += 32) {
            float xv = xt[i];
#pragma unroll
            for (int e = 0; e < NEXP; e++) acc[e] += xv * s_rw[e * DDIM + i];
        }
#pragma unroll
        for (int off = 16; off; off >>= 1)
#pragma unroll
            for (int e = 0; e < NEXP; e++) acc[e] += __shfl_xor_sync(0xffffffffu, acc[e], off);
        if (lane == 0) {
#pragma unroll
            for (int e = 0; e < NEXP; e++) acc[e] += rb[e];
            int e0 = 0; float l0 = acc[0];
#pragma unroll
            for (int e = 1; e < NEXP; e++) if (acc[e] > l0) { l0 = acc[e]; e0 = e; }
            int e1 = (e0 == 0) ? 1 : 0; float l1 = acc[e1];
#pragma unroll
            for (int e = 0; e < NEXP; e++)
                if (e != e0 && acc[e] > l1) { l1 = acc[e]; e1 = e; }
            float w0 = 1.f / (1.f + __expf(l1 - l0));
            g_tok_e[2 * t] = e0;  g_tok_e[2 * t + 1] = e1;
            g_tok_w[2 * t] = w0;  g_tok_w[2 * t + 1] = 1.f - w0;
            atomicAdd(&g_cnt[e0], 1);
            atomicAdd(&g_cnt[e1], 1);
        }
    }

    __syncthreads();
    if (tid == 0) {
        __threadfence();
        int v = atomicAdd(&g_done, 1);
        s_last = (v == (int)gridDim.x - 1);
    }
    __syncthreads();
    if (!s_last) return;
    __threadfence();

    if (tid == 0) {
        int base = 0, nt = 0;
        for (int e = 0; e < NEXP; e++) {
            g_cur[e] = base;
            int tiles = (g_cnt[e] + 127) >> 7;
            for (int i = 0; i < tiles; i++) { g_tile_e[nt] = e; g_tile_r[nt] = base + i * 128; nt++; }
            base += tiles << 7;
        }
        g_nmt = nt;
        g_done = 0;
    }
    __syncthreads();

    for (int t = tid; t < T_TOKENS; t += 256) {
#pragma unroll
        for (int k = 0; k < 2; k++) {
            int e = g_tok_e[2 * t + k];
            int r = atomicAdd(&g_cur[e], 1);
            g_row_token[r] = t;
            g_tok_row[2 * t + k] = r;
        }
    }
}

// ---------------------------------------------------------------------------
// Weight transposes (+fp16 convert) — forked stream; transpose13 split by F-half
// ---------------------------------------------------------------------------
__global__ void transpose13_kernel(const float* __restrict__ w1, const float* __restrict__ w3,
                                   __half* __restrict__ w1t, __half* __restrict__ w3t,
                                   int c_base) {
    __shared__ float t[32][33];
    const int zz = blockIdx.z;
    const float* src = (zz < NEXP) ? w1 : w3;
    __half* dst = (zz < NEXP) ? w1t : w3t;
    const size_t mo = (size_t)(zz & 7) * DDIM * FDIM;
    const int c0 = c_base + blockIdx.x * 32, r0 = blockIdx.y * 32;
    const int tx = threadIdx.x, ty = threadIdx.y;
#pragma unroll
    for (int i = 0; i < 32; i += 8)
        t[ty + i][tx] = src[mo + (size_t)(r0 + ty + i) * FDIM + c0 + tx];
    __syncthreads();
#pragma unroll
    for (int i = 0; i < 32; i += 8)
        dst[mo + (size_t)(c0 + ty + i) * DDIM + r0 + tx] = __float2half_rn(t[tx][ty + i]);
}

__global__ void transpose2_kernel(const float* __restrict__ src, __half* __restrict__ dst) {
    __shared__ float t[32][33];
    const size_t mo = (size_t)blockIdx.z * DDIM * FDIM;
    const int c0 = blockIdx.x * 32, r0 = blockIdx.y * 32;
    const int tx = threadIdx.x, ty = threadIdx.y;
#pragma unroll
    for (int i = 0; i < 32; i += 8)
        t[ty + i][tx] = src[mo + (size_t)(r0 + ty + i) * DDIM + c0 + tx];
    __syncthreads();
#pragma unroll
    for (int i = 0; i < 32; i += 8)
        dst[mo + (size_t)(c0 + ty + i) * FDIM + r0 + tx] = __float2half_rn(t[tx][ty + i]);
}

// ---------------------------------------------------------------------------
// L4: grouped GEMM1 — H = silu(X@w1) * (X@w3)   [fp16 MMA, BK=64]
// 256 threads, 8 warps (2Mx4N), warp 64x32 both gates, 3-stage cp.async.
// ---------------------------------------------------------------------------
__global__ void __launch_bounds__(256, 1)
gemm1_kernel(int n_base) {
    if (blockIdx.x >= g_nmt) return;
    extern __shared__ char smem[];
    const uint32_t sb = smem_u32(smem);
    const int tid = threadIdx.x, wid = tid >> 5, lane = tid & 31;
    const int wm = wid >> 2, wn = wid & 3;
    const int r4 = lane >> 2, c4 = lane & 3;
    const uint32_t xa = (uint32_t)(r4 << 4);

    const int e  = g_tile_e[blockIdx.x];
    const int r0 = g_tile_r[blockIdx.x];
    const int n0 = n_base + blockIdx.y * BN;

    int* s_tok = (int*)smem;
    if (tid < 128) {
        int t = g_row_token[r0 + tid];
        s_tok[tid] = ((unsigned)t < T_TOKENS) ? t : 0;
    }
    __syncthreads();

    const __half* w1e = g_w1t + (size_t)e * FDIM * DDIM + (size_t)n0 * DDIM;
    const __half* w3e = g_w3t + (size_t)e * FDIM * DDIM + (size_t)n0 * DDIM;

    // staging: 1024 chunks (16B) per 16KB region, 4 per thread
    const char* srcA[4]; const char* srcB1[4]; const char* srcB3[4];
    uint32_t dOf[4];
#pragma unroll
    for (int i = 0; i < 4; i++) {
        int idx = tid + i * 256;
        int row = idx >> 3, c = idx & 7;
        dOf[i] = (uint32_t)(row * 128 + ((c * 16) ^ ((row & 7) << 4)));
        srcA[i]  = (const char*)(g_xt + (size_t)s_tok[row] * DDIM + c * 8);
        srcB1[i] = (const char*)(w1e + (size_t)row * DDIM + c * 8);
        srcB3[i] = (const char*)(w3e + (size_t)row * DDIM + c * 8);
    }

    float accU[4][4][4], accV[4][4][4];
#pragma unroll
    for (int i = 0; i < 4; i++)
#pragma unroll
        for (int j = 0; j < 4; j++)
#pragma unroll
            for (int q = 0; q < 4; q++) { accU[i][j][q] = 0.f; accV[i][j][q] = 0.f; }

    const int KS = DDIM / BK;   // 16

#define G1_ISSUE(s)                                                            \
    do {                                                                       \
        uint32_t base_ = sb + 1024 + ((s) % 3) * STAGE1_SZ;                    \
        size_t off_ = (size_t)(s) * 128;                                       \
        _Pragma("unroll")                                                      \
        for (int i_ = 0; i_ < 4; i_++) {                                       \
            CP_ASYNC16(base_ + dOf[i_],         srcA[i_]  + off_);             \
            CP_ASYNC16(base_ + 16384 + dOf[i_], srcB1[i_] + off_);             \
            CP_ASYNC16(base_ + 32768 + dOf[i_], srcB3[i_] + off_);             \
        }                                                                      \
    } while (0)

    G1_ISSUE(0); CP_COMMIT();
    G1_ISSUE(1); CP_COMMIT();

    for (int ks = 0; ks < KS; ks++) {
        CP_WAIT1();
        __syncthreads();
        if (ks + 2 < KS) G1_ISSUE(ks + 2);
        CP_COMMIT();

        const uint32_t sA  = sb + 1024 + (ks % 3) * STAGE1_SZ;
        const uint32_t sB1 = sA + 16384;
        const uint32_t sB3 = sA + 32768;
#pragma unroll
        for (int g = 0; g < 4; g++) {           // four k16 groups per BK=64
            const uint32_t kb = (uint32_t)(g * 32 + 4 * c4);
            const uint32_t k0 = kb ^ xa;
            const uint32_t k1 = (kb + 16) ^ xa;
            uint32_t a[4][4], b1f[4][2], b3f[4][2];
#pragma unroll
            for (int mt = 0; mt < 4; mt++) {
                uint32_t rowb = sA + (uint32_t)((wm * 64 + mt * 16 + r4) * 128);
                a[mt][0] = lds32(rowb + k0);
                a[mt][1] = lds32(rowb + 1024 + k0);
                a[mt][2] = lds32(rowb + k1);
                a[mt][3] = lds32(rowb + 1024 + k1);
            }
#pragma unroll
            for (int nt = 0; nt < 4; nt++) {
                uint32_t nrow = (uint32_t)((wn * 32 + nt * 8 + r4) * 128);
                b1f[nt][0] = lds32(sB1 + nrow + k0);
                b1f[nt][1] = lds32(sB1 + nrow + k1);
                b3f[nt][0] = lds32(sB3 + nrow + k0);
                b3f[nt][1] = lds32(sB3 + nrow + k1);
            }
#pragma unroll
            for (int nt = 0; nt < 4; nt++)
#pragma unroll
                for (int mt = 0; mt < 4; mt++) {
                    mma16(accU[mt][nt], a[mt], b1f[nt][0], b1f[nt][1]);
                    mma16(accV[mt][nt], a[mt], b3f[nt][0], b3f[nt][1]);
                }
        }
    }

    // epilogue: h = silu(u)*v -> fp16 H
#pragma unroll
    for (int mt = 0; mt < 4; mt++) {
#pragma unroll
        for (int nt = 0; nt < 4; nt++) {
#pragma unroll
            for (int half = 0; half < 2; half++) {
                int r = r0 + wm * 64 + mt * 16 + r4 + half * 8;
                int cgl = n0 + wn * 32 + nt * 8 + 2 * c4;
                float u0 = accU[mt][nt][2 * half],     v0 = accV[mt][nt][2 * half];
                float u1 = accU[mt][nt][2 * half + 1], v1 = accV[mt][nt][2 * half + 1];
                __half2 o = __floats2half2_rn(u0 / (1.f + __expf(-u0)) * v0,
                                              u1 / (1.f + __expf(-u1)) * v1);
                *(__half2*)(g_H + (size_t)r * FDIM + cgl) = o;
            }
        }
    }
}

// ---------------------------------------------------------------------------
// L6: grouped GEMM2 — Y = H @ w2   [fp16 MMA, BK=64, occ 2]
// ---------------------------------------------------------------------------
__global__ void __launch_bounds__(256, 2)
gemm2_kernel() {
    if (blockIdx.x >= g_nmt) return;
    extern __shared__ char smem[];
    const uint32_t sb = smem_u32(smem);
    const int tid = threadIdx.x, wid = tid >> 5, lane = tid & 31;
    const int wm = wid >> 2, wn = wid & 3;
    const int r4 = lane >> 2, c4 = lane & 3;
    const uint32_t xa = (uint32_t)(r4 << 4);

    const int e  = g_tile_e[blockIdx.x];
    const int r0 = g_tile_r[blockIdx.x];
    const int n0 = blockIdx.y * BN;

    const __half* w2e = g_w2t + (size_t)e * DDIM * FDIM + (size_t)n0 * FDIM;

    const char* srcA[4]; const char* srcB[4];
    uint32_t dOf[4];
#pragma unroll
    for (int i = 0; i < 4; i++) {
        int idx = tid + i * 256;
        int row = idx >> 3, c = idx & 7;
        dOf[i] = (uint32_t)(row * 128 + ((c * 16) ^ ((row & 7) << 4)));
        srcA[i] = (const char*)(g_H + (size_t)(r0 + row) * FDIM + c * 8);
        srcB[i] = (const char*)(w2e + (size_t)row * FDIM + c * 8);
    }

    float acc[4][4][4];
#pragma unroll
    for (int i = 0; i < 4; i++)
#pragma unroll
        for (int j = 0; j < 4; j++)
#pragma unroll
            for (int q = 0; q < 4; q++) acc[i][j][q] = 0.f;

    const int KS = FDIM / BK;   // 64

#define G2_ISSUE(s)                                                            \
    do {                                                                       \
        uint32_t base_ = sb + 1024 + ((s) % 3) * STAGE2_SZ;                    \
        size_t off_ = (size_t)(s) * 128;                                       \
        _Pragma("unroll")                                                      \
        for (int i_ = 0; i_ < 4; i_++) {                                       \
            CP_ASYNC16(base_ + dOf[i_],         srcA[i_] + off_);              \
            CP_ASYNC16(base_ + 16384 + dOf[i_], srcB[i_] + off_);              \
        }                                                                      \
    } while (0)

    G2_ISSUE(0); CP_COMMIT();
    G2_ISSUE(1); CP_COMMIT();

    for (int ks = 0; ks < KS; ks++) {
        CP_WAIT1();
        __syncthreads();
        if (ks + 2 < KS) G2_ISSUE(ks + 2);
        CP_COMMIT();

        const uint32_t sA = sb + 1024 + (ks % 3) * STAGE2_SZ;
        const uint32_t sB = sA + 16384;
#pragma unroll
        for (int g = 0; g < 4; g++) {
            const uint32_t kb = (uint32_t)(g * 32 + 4 * c4);
            const uint32_t k0 = kb ^ xa;
            const uint32_t k1 = (kb + 16) ^ xa;
            uint32_t a[4][4], bf[4][2];
#pragma unroll
            for (int mt = 0; mt < 4; mt++) {
                uint32_t rowb = sA + (uint32_t)((wm * 64 + mt * 16 + r4) * 128);
                a[mt][0] = lds32(rowb + k0);
                a[mt][1] = lds32(rowb + 1024 + k0);
                a[mt][2] = lds32(rowb + k1);
                a[mt][3] = lds32(rowb + 1024 + k1);
            }
#pragma unroll
            for (int nt = 0; nt < 4; nt++) {
                uint32_t nrow = (uint32_t)((wn * 32 + nt * 8 + r4) * 128);
                bf[nt][0] = lds32(sB + nrow + k0);
                bf[nt][1] = lds32(sB + nrow + k1);
            }
#pragma unroll
            for (int nt = 0; nt < 4; nt++)
#pragma unroll
                for (int mt = 0; mt < 4; mt++)
                    mma16(acc[mt][nt], a[mt], bf[nt][0], bf[nt][1]);
        }
    }

#pragma unroll
    for (int mt = 0; mt < 4; mt++) {
#pragma unroll
        for (int nt = 0; nt < 4; nt++) {
#pragma unroll
            for (int half = 0; half < 2; half++) {
                int r = r0 + wm * 64 + mt * 16 + r4 + half * 8;
                int cgl = n0 + wn * 32 + nt * 8 + 2 * c4;
                float2 o;
                o.x = acc[mt][nt][2 * half];
                o.y = acc[mt][nt][2 * half + 1];
                *(float2*)(g_Y + (size_t)r * DDIM + cgl) = o;
            }
        }
    }
}

// ---------------------------------------------------------------------------
// L7: combine
// ---------------------------------------------------------------------------
__global__ void combine_kernel(float* __restrict__ out) {
    int t = blockIdx.x;
    int d = threadIdx.x * 4;
    float w0 = g_tok_w[2 * t], w1v = g_tok_w[2 * t + 1];
    int   r0 = g_tok_row[2 * t], r1 = g_tok_row[2 * t + 1];
    const float4 a = *(const float4*)(g_Y + (size_t)r0 * DDIM + d);
    const float4 b = *(const float4*)(g_Y + (size_t)r1 * DDIM + d);
    float4 o;
    o.x = w0 * a.x + w1v * b.x;
    o.y = w0 * a.y + w1v * b.y;
    o.z = w0 * a.z + w1v * b.z;
    o.w = w0 * a.w + w1v * b.w;
    *(float4*)(out + (size_t)t * DDIM + d) = o;
}

// ---------------------------------------------------------------------------
// Launcher — split-transpose pipeline; gemm1a is the 4th submitted kernel
// ---------------------------------------------------------------------------
extern "C" void kernel_launch(void* const* d_in, const int* in_sizes, int n_in,
                              void* d_out, int out_size) {
    const float* x  = (const float*)d_in[0];
    const float* rw = (const float*)d_in[1];
    const float* rb = (const float*)d_in[2];
    const float* w1 = (const float*)d_in[3];
    const float* w2 = (const float*)d_in[4];
    const float* w3 = (const float*)d_in[5];
    float* out = (float*)d_out;

    cudaFuncSetAttribute(gemm1_kernel, cudaFuncAttributeMaxDynamicSharedMemorySize, SMEM1_SZ);
    cudaFuncSetAttribute(gemm2_kernel, cudaFuncAttributeMaxDynamicSharedMemorySize, SMEM2_SZ);

    __half *w1t, *w3t, *w2t;
    cudaGetSymbolAddress((void**)&w1t, g_w1t);
    cudaGetSymbolAddress((void**)&w3t, g_w3t);
    cudaGetSymbolAddress((void**)&w2t, g_w2t);

    cudaStream_t s1;
    cudaEvent_t e0, e13a, e13b, e2;
    cudaStreamCreateWithFlags(&s1, cudaStreamNonBlocking);
    cudaEventCreateWithFlags(&e0, cudaEventDisableTiming);
    cudaEventCreateWithFlags(&e13a, cudaEventDisableTiming);
    cudaEventCreateWithFlags(&e13b, cudaEventDisableTiming);
    cudaEventCreateWithFlags(&e2, cudaEventDisableTiming);

    cudaEventRecord(e0, 0);
    cudaStreamWaitEvent(s1, e0, 0);

    convx_init_kernel<<<(T_TOKENS * DDIM / 8) / 256, 256>>>(x);              // #1 main
    router_fused_kernel<<<64, 256>>>(x, rw, rb);                             // #2 main
    transpose13_kernel<<<dim3(64, DDIM / 32, 2 * NEXP), dim3(32, 8), 0, s1>>>(
        w1, w3, w1t, w3t, 0);                                                // #3 s1 (F 0..2047)
    cudaEventRecord(e13a, s1);
    cudaStreamWaitEvent(0, e13a, 0);
    gemm1_kernel<<<dim3(MAX_MT, 16), 256, SMEM1_SZ>>>(0);                    // #4 main (n 0..2047)
    transpose13_kernel<<<dim3(64, DDIM / 32, 2 * NEXP), dim3(32, 8), 0, s1>>>(
        w1, w3, w1t, w3t, 2048);                                             // #5 s1 (F 2048..4095)
    cudaEventRecord(e13b, s1);
    transpose2_kernel<<<dim3(DDIM / 32, FDIM / 32, NEXP), dim3(32, 8), 0, s1>>>(
        w2, w2t);                                                            // #6 s1
    cudaEventRecord(e2, s1);
    cudaStreamWaitEvent(0, e13b, 0);
    gemm1_kernel<<<dim3(MAX_MT, 16), 256, SMEM1_SZ>>>(2048);                 // #7 main (n 2048..4095)
    cudaStreamWaitEvent(0, e2, 0);
    gemm2_kernel<<<dim3(MAX_MT, DDIM / BN), 256, SMEM2_SZ>>>();              // #8 main
    combine_kernel<<<T_TOKENS, 256>>>(out);                                  // #9 main
}

// round 10
// speedup vs baseline: 2.1697x; 1.0628x over previous
#include <cuda_runtime.h>
#include <cuda_fp16.h>
#include <cstdint>

// ---------------------------------------------------------------------------
// Problem constants
// ---------------------------------------------------------------------------
#define T_TOKENS 4096
#define DDIM 1024
#define FDIM 4096
#define NEXP 8
#define BM 128
#define BK 64
#define MAX_MT 72
#define ROWS_CAP (MAX_MT * 128)

// ---------------------------------------------------------------------------
// Device scratch (fp16 operands, fp32 outputs)
// ---------------------------------------------------------------------------
__device__ int    g_cnt[NEXP];
__device__ int    g_cur[NEXP];
__device__ int    g_done;
__device__ int    g_nmt;
__device__ int    g_tile_e[MAX_MT];
__device__ int    g_tile_r[MAX_MT];
__device__ int    g_row_token[ROWS_CAP];
__device__ int    g_tok_e[T_TOKENS * 2];
__device__ int    g_tok_row[T_TOKENS * 2];
__device__ float  g_tok_w[T_TOKENS * 2];
__device__ __half g_H[(size_t)ROWS_CAP * FDIM];
__device__ float  g_Y[(size_t)ROWS_CAP * DDIM];
__device__ __half g_xt[(size_t)T_TOKENS * DDIM];
__device__ __half g_w1t[(size_t)NEXP * DDIM * FDIM];
__device__ __half g_w3t[(size_t)NEXP * DDIM * FDIM];
__device__ __half g_w2t[(size_t)NEXP * DDIM * FDIM];

// ---------------------------------------------------------------------------
// Helpers
// ---------------------------------------------------------------------------
__device__ __forceinline__ uint32_t smem_u32(const void* p) {
    uint32_t a;
    asm("{ .reg .u64 t; cvta.to.shared.u64 t, %1; cvt.u32.u64 %0, t; }" : "=r"(a) : "l"(p));
    return a;
}
__device__ __forceinline__ uint32_t lds32(uint32_t a) {
    uint32_t v;
    asm volatile("ld.shared.b32 %0, [%1];" : "=r"(v) : "r"(a));
    return v;
}
__device__ __forceinline__ uint32_t h2u(__half2 h) {
    uint32_t u;
    __builtin_memcpy(&u, &h, 4);
    return u;
}
__device__ __forceinline__ void mma16(float* d, const uint32_t* a, uint32_t b0, uint32_t b1) {
    asm volatile(
        "mma.sync.aligned.m16n8k16.row.col.f32.f16.f16.f32 "
        "{%0,%1,%2,%3}, {%4,%5,%6,%7}, {%8,%9}, {%0,%1,%2,%3};"
        : "+f"(d[0]), "+f"(d[1]), "+f"(d[2]), "+f"(d[3])
        : "r"(a[0]), "r"(a[1]), "r"(a[2]), "r"(a[3]), "r"(b0), "r"(b1));
}
#define CP_ASYNC16(dst, src) \
    asm volatile("cp.async.cg.shared.global [%0], [%1], 16;" :: "r"(dst), "l"(src))
#define CP_COMMIT() asm volatile("cp.async.commit_group;" ::: "memory")
#define CP_WAIT1()  asm volatile("cp.async.wait_group 1;" ::: "memory")

// Rows: 128B (64 fp16), SW128 swizzle  off = r*128 + (b ^ ((r&7)<<4)).
// Conflict-free for staging chunks and fragment loads (verified R8/R9).
#define STAGE1_SZ 32768   // A(16K) + B1(8K) + B3(8K)
#define STAGE2_SZ 32768   // A(16K) + B(16K)
#define SMEM1_SZ (1024 + 3 * STAGE1_SZ)   // 99328/CTA, occ 2
#define SMEM2_SZ (1024 + 3 * STAGE2_SZ)

// ---------------------------------------------------------------------------
// L1: convx + init — x -> fp16
// ---------------------------------------------------------------------------
__global__ void convx_init_kernel(const float* __restrict__ x) {
    int i = blockIdx.x * blockDim.x + threadIdx.x;   // 8 elems/thread
    if (blockIdx.x == 0) {
        if (threadIdx.x < NEXP) g_cnt[threadIdx.x] = 0;
        if (threadIdx.x == NEXP) g_done = 0;
    }
    const float4 v0 = ((const float4*)x)[2 * i];
    const float4 v1 = ((const float4*)x)[2 * i + 1];
    uint4 o;
    o.x = h2u(__floats2half2_rn(v0.x, v0.y));
    o.y = h2u(__floats2half2_rn(v0.z, v0.w));
    o.z = h2u(__floats2half2_rn(v1.x, v1.y));
    o.w = h2u(__floats2half2_rn(v1.z, v1.w));
    ((uint4*)g_xt)[i] = o;
}

// ---------------------------------------------------------------------------
// L2: fused router + scan + scatter (last-CTA pattern); 64 CTAs
// ---------------------------------------------------------------------------
__global__ void __launch_bounds__(256)
router_fused_kernel(const float* __restrict__ x, const float* __restrict__ rw,
                    const float* __restrict__ rb) {
    __shared__ float s_rw[NEXP * DDIM];
    __shared__ int s_last;
    const int tid = threadIdx.x, wid = tid >> 5, lane = tid & 31;

    for (int i = tid; i < NEXP * DDIM / 2; i += 256)
        ((float2*)s_rw)[i] = ((const float2*)rw)[i];
    __syncthreads();

    const int tbase = blockIdx.x * 64 + wid * 8;
    for (int j = 0; j < 8; j++) {
        const int t = tbase + j;
        const float* xt = x + (size_t)t * DDIM;
        float acc[NEXP];
#pragma unroll
        for (int e = 0; e < NEXP; e++) acc[e] = 0.f;
        for (int i = lane; i < DDIM; i += 32) {
            float xv = xt[i];
#pragma unroll
            for (int e = 0; e < NEXP; e++) acc[e] += xv * s_rw[e * DDIM + i];
        }
#pragma unroll
        for (int off = 16; off; off >>= 1)
#pragma unroll
            for (int e = 0; e < NEXP; e++) acc[e] += __shfl_xor_sync(0xffffffffu, acc[e], off);
        if (lane == 0) {
#pragma unroll
            for (int e = 0; e < NEXP; e++) acc[e] += rb[e];
            int e0 = 0; float l0 = acc[0];
#pragma unroll
            for (int e = 1; e < NEXP; e++) if (acc[e] > l0) { l0 = acc[e]; e0 = e; }
            int e1 = (e0 == 0) ? 1 : 0; float l1 = acc[e1];
#pragma unroll
            for (int e = 0; e < NEXP; e++)
                if (e != e0 && acc[e] > l1) { l1 = acc[e]; e1 = e; }
            float w0 = 1.f / (1.f + __expf(l1 - l0));
            g_tok_e[2 * t] = e0;  g_tok_e[2 * t + 1] = e1;
            g_tok_w[2 * t] = w0;  g_tok_w[2 * t + 1] = 1.f - w0;
            atomicAdd(&g_cnt[e0], 1);
            atomicAdd(&g_cnt[e1], 1);
        }
    }

    __syncthreads();
    if (tid == 0) {
        __threadfence();
        int v = atomicAdd(&g_done, 1);
        s_last = (v == (int)gridDim.x - 1);
    }
    __syncthreads();
    if (!s_last) return;
    __threadfence();

    if (tid == 0) {
        int base = 0, nt = 0;
        for (int e = 0; e < NEXP; e++) {
            g_cur[e] = base;
            int tiles = (g_cnt[e] + 127) >> 7;
            for (int i = 0; i < tiles; i++) { g_tile_e[nt] = e; g_tile_r[nt] = base + i * 128; nt++; }
            base += tiles << 7;
        }
        g_nmt = nt;
        g_done = 0;
    }
    __syncthreads();

    for (int t = tid; t < T_TOKENS; t += 256) {
#pragma unroll
        for (int k = 0; k < 2; k++) {
            int e = g_tok_e[2 * t + k];
            int r = atomicAdd(&g_cur[e], 1);
            g_row_token[r] = t;
            g_tok_row[2 * t + k] = r;
        }
    }
}

// ---------------------------------------------------------------------------
// Weight transposes (+fp16 convert) — forked stream; transpose13 split by F-half
// ---------------------------------------------------------------------------
__global__ void transpose13_kernel(const float* __restrict__ w1, const float* __restrict__ w3,
                                   __half* __restrict__ w1t, __half* __restrict__ w3t,
                                   int c_base) {
    __shared__ float t[32][33];
    const int zz = blockIdx.z;
    const float* src = (zz < NEXP) ? w1 : w3;
    __half* dst = (zz < NEXP) ? w1t : w3t;
    const size_t mo = (size_t)(zz & 7) * DDIM * FDIM;
    const int c0 = c_base + blockIdx.x * 32, r0 = blockIdx.y * 32;
    const int tx = threadIdx.x, ty = threadIdx.y;
#pragma unroll
    for (int i = 0; i < 32; i += 8)
        t[ty + i][tx] = src[mo + (size_t)(r0 + ty + i) * FDIM + c0 + tx];
    __syncthreads();
#pragma unroll
    for (int i = 0; i < 32; i += 8)
        dst[mo + (size_t)(c0 + ty + i) * DDIM + r0 + tx] = __float2half_rn(t[tx][ty + i]);
}

__global__ void transpose2_kernel(const float* __restrict__ src, __half* __restrict__ dst) {
    __shared__ float t[32][33];
    const size_t mo = (size_t)blockIdx.z * DDIM * FDIM;
    const int c0 = blockIdx.x * 32, r0 = blockIdx.y * 32;
    const int tx = threadIdx.x, ty = threadIdx.y;
#pragma unroll
    for (int i = 0; i < 32; i += 8)
        t[ty + i][tx] = src[mo + (size_t)(r0 + ty + i) * DDIM + c0 + tx];
    __syncthreads();
#pragma unroll
    for (int i = 0; i < 32; i += 8)
        dst[mo + (size_t)(c0 + ty + i) * FDIM + r0 + tx] = __float2half_rn(t[tx][ty + i]);
}

// ---------------------------------------------------------------------------
// L4: grouped GEMM1 — H = silu(X@w1) * (X@w3)   [fp16 MMA, BK=64, occ 2]
// CTA tile 128x64, 8 warps (2M x 4N), warp tile 64x16, 64 accs/thread.
// ---------------------------------------------------------------------------
__global__ void __launch_bounds__(256, 2)
gemm1_kernel(int n_base) {
    if (blockIdx.x >= g_nmt) return;
    extern __shared__ char smem[];
    const uint32_t sb = smem_u32(smem);
    const int tid = threadIdx.x, wid = tid >> 5, lane = tid & 31;
    const int wm = wid >> 2, wn = wid & 3;
    const int r4 = lane >> 2, c4 = lane & 3;
    const uint32_t xa = (uint32_t)(r4 << 4);

    const int e  = g_tile_e[blockIdx.x];
    const int r0 = g_tile_r[blockIdx.x];
    const int n0 = n_base + blockIdx.y * 64;

    int* s_tok = (int*)smem;
    if (tid < 128) {
        int t = g_row_token[r0 + tid];
        s_tok[tid] = ((unsigned)t < T_TOKENS) ? t : 0;
    }
    __syncthreads();

    const __half* w1e = g_w1t + (size_t)e * FDIM * DDIM + (size_t)n0 * DDIM;
    const ptrdiff_t d31 = (const char*)g_w3t - (const char*)g_w1t;   // w3 = w1 + d31

    // staging: A 1024 chunks (4/thread), B1 512 chunks (2/thread), B3 mirrors B1
    const char* srcA[4]; const char* srcB1[2];
    uint32_t dOfA[4], dOfB[2];
#pragma unroll
    for (int i = 0; i < 4; i++) {
        int idx = tid + i * 256;
        int row = idx >> 3, c = idx & 7;
        dOfA[i] = (uint32_t)(row * 128 + ((c * 16) ^ ((row & 7) << 4)));
        srcA[i] = (const char*)(g_xt + (size_t)s_tok[row] * DDIM + c * 8);
    }
#pragma unroll
    for (int i = 0; i < 2; i++) {
        int idx = tid + i * 256;
        int row = idx >> 3, c = idx & 7;                 // row 0..63
        dOfB[i] = (uint32_t)(row * 128 + ((c * 16) ^ ((row & 7) << 4)));
        srcB1[i] = (const char*)(w1e + (size_t)row * DDIM + c * 8);
    }

    float accU[4][2][4], accV[4][2][4];
#pragma unroll
    for (int i = 0; i < 4; i++)
#pragma unroll
        for (int j = 0; j < 2; j++)
#pragma unroll
            for (int q = 0; q < 4; q++) { accU[i][j][q] = 0.f; accV[i][j][q] = 0.f; }

    const int KS = DDIM / BK;   // 16

#define G1_ISSUE(s)                                                            \
    do {                                                                       \
        uint32_t base_ = sb + 1024 + ((s) % 3) * STAGE1_SZ;                    \
        size_t off_ = (size_t)(s) * 128;                                       \
        _Pragma("unroll")                                                      \
        for (int i_ = 0; i_ < 4; i_++)                                         \
            CP_ASYNC16(base_ + dOfA[i_], srcA[i_] + off_);                     \
        _Pragma("unroll")                                                      \
        for (int i_ = 0; i_ < 2; i_++) {                                       \
            CP_ASYNC16(base_ + 16384 + dOfB[i_], srcB1[i_] + off_);            \
            CP_ASYNC16(base_ + 24576 + dOfB[i_], srcB1[i_] + d31 + off_);      \
        }                                                                      \
    } while (0)

    G1_ISSUE(0); CP_COMMIT();
    G1_ISSUE(1); CP_COMMIT();

    for (int ks = 0; ks < KS; ks++) {
        CP_WAIT1();
        __syncthreads();
        if (ks + 2 < KS) G1_ISSUE(ks + 2);
        CP_COMMIT();

        const uint32_t sA  = sb + 1024 + (ks % 3) * STAGE1_SZ;
        const uint32_t sB1 = sA + 16384;
        const uint32_t sB3 = sA + 24576;
#pragma unroll
        for (int g = 0; g < 4; g++) {           // four k16 groups per BK=64
            const uint32_t kb = (uint32_t)(g * 32 + 4 * c4);
            const uint32_t k0 = kb ^ xa;
            const uint32_t k1 = (kb + 16) ^ xa;
            uint32_t a[4][4], b1f[2][2], b3f[2][2];
#pragma unroll
            for (int mt = 0; mt < 4; mt++) {
                uint32_t rowb = sA + (uint32_t)((wm * 64 + mt * 16 + r4) * 128);
                a[mt][0] = lds32(rowb + k0);
                a[mt][1] = lds32(rowb + 1024 + k0);
                a[mt][2] = lds32(rowb + k1);
                a[mt][3] = lds32(rowb + 1024 + k1);
            }
#pragma unroll
            for (int nt = 0; nt < 2; nt++) {
                uint32_t nrow = (uint32_t)((wn * 16 + nt * 8 + r4) * 128);
                b1f[nt][0] = lds32(sB1 + nrow + k0);
                b1f[nt][1] = lds32(sB1 + nrow + k1);
                b3f[nt][0] = lds32(sB3 + nrow + k0);
                b3f[nt][1] = lds32(sB3 + nrow + k1);
            }
#pragma unroll
            for (int nt = 0; nt < 2; nt++)
#pragma unroll
                for (int mt = 0; mt < 4; mt++) {
                    mma16(accU[mt][nt], a[mt], b1f[nt][0], b1f[nt][1]);
                    mma16(accV[mt][nt], a[mt], b3f[nt][0], b3f[nt][1]);
                }
        }
    }

    // epilogue: h = silu(u)*v -> fp16 H
#pragma unroll
    for (int mt = 0; mt < 4; mt++) {
#pragma unroll
        for (int nt = 0; nt < 2; nt++) {
#pragma unroll
            for (int half = 0; half < 2; half++) {
                int r = r0 + wm * 64 + mt * 16 + r4 + half * 8;
                int cgl = n0 + wn * 16 + nt * 8 + 2 * c4;
                float u0 = accU[mt][nt][2 * half],     v0 = accV[mt][nt][2 * half];
                float u1 = accU[mt][nt][2 * half + 1], v1 = accV[mt][nt][2 * half + 1];
                __half2 o = __floats2half2_rn(u0 / (1.f + __expf(-u0)) * v0,
                                              u1 / (1.f + __expf(-u1)) * v1);
                *(__half2*)(g_H + (size_t)r * FDIM + cgl) = o;
            }
        }
    }
}

// ---------------------------------------------------------------------------
// L6: grouped GEMM2 — Y = H @ w2   [fp16 MMA, BK=64, occ 2]  (unchanged R9)
// ---------------------------------------------------------------------------
__global__ void __launch_bounds__(256, 2)
gemm2_kernel() {
    if (blockIdx.x >= g_nmt) return;
    extern __shared__ char smem[];
    const uint32_t sb = smem_u32(smem);
    const int tid = threadIdx.x, wid = tid >> 5, lane = tid & 31;
    const int wm = wid >> 2, wn = wid & 3;
    const int r4 = lane >> 2, c4 = lane & 3;
    const uint32_t xa = (uint32_t)(r4 << 4);

    const int e  = g_tile_e[blockIdx.x];
    const int r0 = g_tile_r[blockIdx.x];
    const int n0 = blockIdx.y * 128;

    const __half* w2e = g_w2t + (size_t)e * DDIM * FDIM + (size_t)n0 * FDIM;

    const char* srcA[4]; const char* srcB[4];
    uint32_t dOf[4];
#pragma unroll
    for (int i = 0; i < 4; i++) {
        int idx = tid + i * 256;
        int row = idx >> 3, c = idx & 7;
        dOf[i] = (uint32_t)(row * 128 + ((c * 16) ^ ((row & 7) << 4)));
        srcA[i] = (const char*)(g_H + (size_t)(r0 + row) * FDIM + c * 8);
        srcB[i] = (const char*)(w2e + (size_t)row * FDIM + c * 8);
    }

    float acc[4][4][4];
#pragma unroll
    for (int i = 0; i < 4; i++)
#pragma unroll
        for (int j = 0; j < 4; j++)
#pragma unroll
            for (int q = 0; q < 4; q++) acc[i][j][q] = 0.f;

    const int KS = FDIM / BK;   // 64

#define G2_ISSUE(s)                                                            \
    do {                                                                       \
        uint32_t base_ = sb + 1024 + ((s) % 3) * STAGE2_SZ;                    \
        size_t off_ = (size_t)(s) * 128;                                       \
        _Pragma("unroll")                                                      \
        for (int i_ = 0; i_ < 4; i_++) {                                       \
            CP_ASYNC16(base_ + dOf[i_],         srcA[i_] + off_);              \
            CP_ASYNC16(base_ + 16384 + dOf[i_], srcB[i_] + off_);              \
        }                                                                      \
    } while (0)

    G2_ISSUE(0); CP_COMMIT();
    G2_ISSUE(1); CP_COMMIT();

    for (int ks = 0; ks < KS; ks++) {
        CP_WAIT1();
        __syncthreads();
        if (ks + 2 < KS) G2_ISSUE(ks + 2);
        CP_COMMIT();

        const uint32_t sA = sb + 1024 + (ks % 3) * STAGE2_SZ;
        const uint32_t sB = sA + 16384;
#pragma unroll
        for (int g = 0; g < 4; g++) {
            const uint32_t kb = (uint32_t)(g * 32 + 4 * c4);
            const uint32_t k0 = kb ^ xa;
            const uint32_t k1 = (kb + 16) ^ xa;
            uint32_t a[4][4], bf[4][2];
#pragma unroll
            for (int mt = 0; mt < 4; mt++) {
                uint32_t rowb = sA + (uint32_t)((wm * 64 + mt * 16 + r4) * 128);
                a[mt][0] = lds32(rowb + k0);
                a[mt][1] = lds32(rowb + 1024 + k0);
                a[mt][2] = lds32(rowb + k1);
                a[mt][3] = lds32(rowb + 1024 + k1);
            }
#pragma unroll
            for (int nt = 0; nt < 4; nt++) {
                uint32_t nrow = (uint32_t)((wn * 32 + nt * 8 + r4) * 128);
                bf[nt][0] = lds32(sB + nrow + k0);
                bf[nt][1] = lds32(sB + nrow + k1);
            }
#pragma unroll
            for (int nt = 0; nt < 4; nt++)
#pragma unroll
                for (int mt = 0; mt < 4; mt++)
                    mma16(acc[mt][nt], a[mt], bf[nt][0], bf[nt][1]);
        }
    }

#pragma unroll
    for (int mt = 0; mt < 4; mt++) {
#pragma unroll
        for (int nt = 0; nt < 4; nt++) {
#pragma unroll
            for (int half = 0; half < 2; half++) {
                int r = r0 + wm * 64 + mt * 16 + r4 + half * 8;
                int cgl = n0 + wn * 32 + nt * 8 + 2 * c4;
                float2 o;
                o.x = acc[mt][nt][2 * half];
                o.y = acc[mt][nt][2 * half + 1];
                *(float2*)(g_Y + (size_t)r * DDIM + cgl) = o;
            }
        }
    }
}

// ---------------------------------------------------------------------------
// L7: combine
// ---------------------------------------------------------------------------
__global__ void combine_kernel(float* __restrict__ out) {
    int t = blockIdx.x;
    int d = threadIdx.x * 4;
    float w0 = g_tok_w[2 * t], w1v = g_tok_w[2 * t + 1];
    int   r0 = g_tok_row[2 * t], r1 = g_tok_row[2 * t + 1];
    const float4 a = *(const float4*)(g_Y + (size_t)r0 * DDIM + d);
    const float4 b = *(const float4*)(g_Y + (size_t)r1 * DDIM + d);
    float4 o;
    o.x = w0 * a.x + w1v * b.x;
    o.y = w0 * a.y + w1v * b.y;
    o.z = w0 * a.z + w1v * b.z;
    o.w = w0 * a.w + w1v * b.w;
    *(float4*)(out + (size_t)t * DDIM + d) = o;
}

// ---------------------------------------------------------------------------
// Launcher — split-transpose pipeline; gemm1a is the 4th submitted kernel
// ---------------------------------------------------------------------------
extern "C" void kernel_launch(void* const* d_in, const int* in_sizes, int n_in,
                              void* d_out, int out_size) {
    const float* x  = (const float*)d_in[0];
    const float* rw = (const float*)d_in[1];
    const float* rb = (const float*)d_in[2];
    const float* w1 = (const float*)d_in[3];
    const float* w2 = (const float*)d_in[4];
    const float* w3 = (const float*)d_in[5];
    float* out = (float*)d_out;

    cudaFuncSetAttribute(gemm1_kernel, cudaFuncAttributeMaxDynamicSharedMemorySize, SMEM1_SZ);
    cudaFuncSetAttribute(gemm2_kernel, cudaFuncAttributeMaxDynamicSharedMemorySize, SMEM2_SZ);

    __half *w1t, *w3t, *w2t;
    cudaGetSymbolAddress((void**)&w1t, g_w1t);
    cudaGetSymbolAddress((void**)&w3t, g_w3t);
    cudaGetSymbolAddress((void**)&w2t, g_w2t);

    cudaStream_t s1;
    cudaEvent_t e0, e13a, e13b, e2;
    cudaStreamCreateWithFlags(&s1, cudaStreamNonBlocking);
    cudaEventCreateWithFlags(&e0, cudaEventDisableTiming);
    cudaEventCreateWithFlags(&e13a, cudaEventDisableTiming);
    cudaEventCreateWithFlags(&e13b, cudaEventDisableTiming);
    cudaEventCreateWithFlags(&e2, cudaEventDisableTiming);

    cudaEventRecord(e0, 0);
    cudaStreamWaitEvent(s1, e0, 0);

    convx_init_kernel<<<(T_TOKENS * DDIM / 8) / 256, 256>>>(x);              // #1 main
    router_fused_kernel<<<64, 256>>>(x, rw, rb);                             // #2 main
    transpose13_kernel<<<dim3(64, DDIM / 32, 2 * NEXP), dim3(32, 8), 0, s1>>>(
        w1, w3, w1t, w3t, 0);                                                // #3 s1 (F 0..2047)
    cudaEventRecord(e13a, s1);
    cudaStreamWaitEvent(0, e13a, 0);
    gemm1_kernel<<<dim3(MAX_MT, 32), 256, SMEM1_SZ>>>(0);                    // #4 main (n 0..2047)
    transpose13_kernel<<<dim3(64, DDIM / 32, 2 * NEXP), dim3(32, 8), 0, s1>>>(
        w1, w3, w1t, w3t, 2048);                                             // #5 s1 (F 2048..4095)
    cudaEventRecord(e13b, s1);
    transpose2_kernel<<<dim3(DDIM / 32, FDIM / 32, NEXP), dim3(32, 8), 0, s1>>>(
        w2, w2t);                                                            // #6 s1
    cudaEventRecord(e2, s1);
    cudaStreamWaitEvent(0, e13b, 0);
    gemm1_kernel<<<dim3(MAX_MT, 32), 256, SMEM1_SZ>>>(2048);                 // #7 main (n 2048..4095)
    cudaStreamWaitEvent(0, e2, 0);
    gemm2_kernel<<<dim3(MAX_MT, DDIM / 128), 256, SMEM2_SZ>>>();             // #8 main
    combine_kernel<<<T_TOKENS, 256>>>(out);                                  // #9 main
}

// round 12
// speedup vs baseline: 2.1824x; 1.0058x over previous
#include <cuda_runtime.h>
#include <cuda_fp16.h>
#include <cstdint>

// ---------------------------------------------------------------------------
// Problem constants
// ---------------------------------------------------------------------------
#define T_TOKENS 4096
#define DDIM 1024
#define FDIM 4096
#define NEXP 8
#define BM 128
#define BK 64
#define MAX_MT 72
#define ROWS_CAP (MAX_MT * 128)

// ---------------------------------------------------------------------------
// Device scratch (fp16 operands, fp32 outputs)
// ---------------------------------------------------------------------------
__device__ int    g_cnt[NEXP];
__device__ int    g_cur[NEXP];
__device__ int    g_done;
__device__ int    g_nmt;
__device__ int    g_tile_e[MAX_MT];
__device__ int    g_tile_r[MAX_MT];
__device__ int    g_row_token[ROWS_CAP];
__device__ int    g_tok_e[T_TOKENS * 2];
__device__ int    g_tok_row[T_TOKENS * 2];
__device__ float  g_tok_w[T_TOKENS * 2];
__device__ __half g_H[(size_t)ROWS_CAP * FDIM];
__device__ float  g_Y1[(size_t)ROWS_CAP * DDIM];
__device__ float  g_Y2[(size_t)ROWS_CAP * DDIM];
__device__ __half g_xt[(size_t)T_TOKENS * DDIM];
__device__ __half g_w1t[(size_t)NEXP * DDIM * FDIM];
__device__ __half g_w3t[(size_t)NEXP * DDIM * FDIM];
__device__ __half g_w2t[(size_t)NEXP * DDIM * FDIM];

// ---------------------------------------------------------------------------
// Helpers
// ---------------------------------------------------------------------------
__device__ __forceinline__ uint32_t smem_u32(const void* p) {
    uint32_t a;
    asm("{ .reg .u64 t; cvta.to.shared.u64 t, %1; cvt.u32.u64 %0, t; }" : "=r"(a) : "l"(p));
    return a;
}
__device__ __forceinline__ uint32_t lds32(uint32_t a) {
    uint32_t v;
    asm volatile("ld.shared.b32 %0, [%1];" : "=r"(v) : "r"(a));
    return v;
}
__device__ __forceinline__ uint32_t h2u(__half2 h) {
    uint32_t u;
    __builtin_memcpy(&u, &h, 4);
    return u;
}
__device__ __forceinline__ void mma16(float* d, const uint32_t* a, uint32_t b0, uint32_t b1) {
    asm volatile(
        "mma.sync.aligned.m16n8k16.row.col.f32.f16.f16.f32 "
        "{%0,%1,%2,%3}, {%4,%5,%6,%7}, {%8,%9}, {%0,%1,%2,%3};"
        : "+f"(d[0]), "+f"(d[1]), "+f"(d[2]), "+f"(d[3])
        : "r"(a[0]), "r"(a[1]), "r"(a[2]), "r"(a[3]), "r"(b0), "r"(b1));
}
#define CP_ASYNC16(dst, src) \
    asm volatile("cp.async.cg.shared.global [%0], [%1], 16;" :: "r"(dst), "l"(src))
#define CP_COMMIT() asm volatile("cp.async.commit_group;" ::: "memory")
#define CP_WAIT1()  asm volatile("cp.async.wait_group 1;" ::: "memory")

// Rows: 128B (64 fp16), SW128 swizzle  off = r*128 + (b ^ ((r&7)<<4)).
// Conflict-free for staging chunks and fragment loads (verified R8-R10).
#define STAGE1_SZ 32768   // A(16K) + B1(8K) + B3(8K)
#define STAGE2_SZ 32768   // A(16K) + B(16K)
#define SMEM1_SZ (1024 + 3 * STAGE1_SZ)   // 99328/CTA, occ 2
#define SMEM2_SZ (1024 + 3 * STAGE2_SZ)

// ---------------------------------------------------------------------------
// L1: convx + init — x -> fp16, zero counters
// ---------------------------------------------------------------------------
__global__ void convx_init_kernel(const float* __restrict__ x) {
    int i = blockIdx.x * blockDim.x + threadIdx.x;   // 8 elems/thread
    if (blockIdx.x == 0) {
        if (threadIdx.x < NEXP) g_cnt[threadIdx.x] = 0;
        if (threadIdx.x == NEXP) g_done = 0;
    }
    const float4 v0 = ((const float4*)x)[2 * i];
    const float4 v1 = ((const float4*)x)[2 * i + 1];
    uint4 o;
    o.x = h2u(__floats2half2_rn(v0.x, v0.y));
    o.y = h2u(__floats2half2_rn(v0.z, v0.w));
    o.z = h2u(__floats2half2_rn(v1.x, v1.y));
    o.w = h2u(__floats2half2_rn(v1.z, v1.w));
    ((uint4*)g_xt)[i] = o;
}

// ---------------------------------------------------------------------------
// L2: fused router + scan + scatter (last-CTA pattern); 64 CTAs
// ---------------------------------------------------------------------------
__global__ void __launch_bounds__(256)
router_fused_kernel(const float* __restrict__ x, const float* __restrict__ rw,
                    const float* __restrict__ rb) {
    __shared__ float s_rw[NEXP * DDIM];
    __shared__ int s_last;
    const int tid = threadIdx.x, wid = tid >> 5, lane = tid & 31;

    for (int i = tid; i < NEXP * DDIM / 2; i += 256)
        ((float2*)s_rw)[i] = ((const float2*)rw)[i];
    __syncthreads();

    const int tbase = blockIdx.x * 64 + wid * 8;
    for (int j = 0; j < 8; j++) {
        const int t = tbase + j;
        const float* xt = x + (size_t)t * DDIM;
        float acc[NEXP];
#pragma unroll
        for (int e = 0; e < NEXP; e++) acc[e] = 0.f;
        for (int i = lane; i < DDIM; i += 32) {
            float xv = xt[i];
#pragma unroll
            for (int e = 0; e < NEXP; e++) acc[e] += xv * s_rw[e * DDIM + i];
        }
#pragma unroll
        for (int off = 16; off; off >>= 1)
#pragma unroll
            for (int e = 0; e < NEXP; e++) acc[e] += __shfl_xor_sync(0xffffffffu, acc[e], off);
        if (lane == 0) {
#pragma unroll
            for (int e = 0; e < NEXP; e++) acc[e] += rb[e];
            int e0 = 0; float l0 = acc[0];
#pragma unroll
            for (int e = 1; e < NEXP; e++) if (acc[e] > l0) { l0 = acc[e]; e0 = e; }
            int e1 = (e0 == 0) ? 1 : 0; float l1 = acc[e1];
#pragma unroll
            for (int e = 0; e < NEXP; e++)
                if (e != e0 && acc[e] > l1) { l1 = acc[e]; e1 = e; }
            float w0 = 1.f / (1.f + __expf(l1 - l0));
            g_tok_e[2 * t] = e0;  g_tok_e[2 * t + 1] = e1;
            g_tok_w[2 * t] = w0;  g_tok_w[2 * t + 1] = 1.f - w0;
            atomicAdd(&g_cnt[e0], 1);
            atomicAdd(&g_cnt[e1], 1);
        }
    }

    __syncthreads();
    if (tid == 0) {
        __threadfence();
        int v = atomicAdd(&g_done, 1);
        s_last = (v == (int)gridDim.x - 1);
    }
    __syncthreads();
    if (!s_last) return;
    __threadfence();

    if (tid == 0) {
        int base = 0, nt = 0;
        for (int e = 0; e < NEXP; e++) {
            g_cur[e] = base;
            int tiles = (g_cnt[e] + 127) >> 7;
            for (int i = 0; i < tiles; i++) { g_tile_e[nt] = e; g_tile_r[nt] = base + i * 128; nt++; }
            base += tiles << 7;
        }
        g_nmt = nt;
        g_done = 0;
    }
    __syncthreads();

    for (int t = tid; t < T_TOKENS; t += 256) {
#pragma unroll
        for (int k = 0; k < 2; k++) {
            int e = g_tok_e[2 * t + k];
            int r = atomicAdd(&g_cur[e], 1);
            g_row_token[r] = t;
            g_tok_row[2 * t + k] = r;
        }
    }
}

// ---------------------------------------------------------------------------
// Weight transposes (+fp16 convert) — forked stream; transpose13 split by F-half
// ---------------------------------------------------------------------------
__global__ void transpose13_kernel(const float* __restrict__ w1, const float* __restrict__ w3,
                                   __half* __restrict__ w1t, __half* __restrict__ w3t,
                                   int c_base) {
    __shared__ float t[32][33];
    const int zz = blockIdx.z;
    const float* src = (zz < NEXP) ? w1 : w3;
    __half* dst = (zz < NEXP) ? w1t : w3t;
    const size_t mo = (size_t)(zz & 7) * DDIM * FDIM;
    const int c0 = c_base + blockIdx.x * 32, r0 = blockIdx.y * 32;
    const int tx = threadIdx.x, ty = threadIdx.y;
#pragma unroll
    for (int i = 0; i < 32; i += 8)
        t[ty + i][tx] = src[mo + (size_t)(r0 + ty + i) * FDIM + c0 + tx];
    __syncthreads();
#pragma unroll
    for (int i = 0; i < 32; i += 8)
        dst[mo + (size_t)(c0 + ty + i) * DDIM + r0 + tx] = __float2half_rn(t[tx][ty + i]);
}

__global__ void transpose2_kernel(const float* __restrict__ src, __half* __restrict__ dst) {
    __shared__ float t[32][33];
    const size_t mo = (size_t)blockIdx.z * DDIM * FDIM;
    const int c0 = blockIdx.x * 32, r0 = blockIdx.y * 32;
    const int tx = threadIdx.x, ty = threadIdx.y;
#pragma unroll
    for (int i = 0; i < 32; i += 8)
        t[ty + i][tx] = src[mo + (size_t)(r0 + ty + i) * DDIM + c0 + tx];
    __syncthreads();
#pragma unroll
    for (int i = 0; i < 32; i += 8)
        dst[mo + (size_t)(c0 + ty + i) * FDIM + r0 + tx] = __float2half_rn(t[tx][ty + i]);
}

// ---------------------------------------------------------------------------
// GEMM1 — H = silu(X@w1) * (X@w3)   [fp16 MMA, BK=64, occ 2]
// CTA tile 128x64, 8 warps (2M x 4N), warp tile 64x16.
// ---------------------------------------------------------------------------
__global__ void __launch_bounds__(256, 2)
gemm1_kernel(int n_base) {
    if (blockIdx.x >= g_nmt) return;
    extern __shared__ char smem[];
    const uint32_t sb = smem_u32(smem);
    const int tid = threadIdx.x, wid = tid >> 5, lane = tid & 31;
    const int wm = wid >> 2, wn = wid & 3;
    const int r4 = lane >> 2, c4 = lane & 3;
    const uint32_t xa = (uint32_t)(r4 << 4);

    const int e  = g_tile_e[blockIdx.x];
    const int r0 = g_tile_r[blockIdx.x];
    const int n0 = n_base + blockIdx.y * 64;

    int* s_tok = (int*)smem;
    if (tid < 128) {
        int t = g_row_token[r0 + tid];
        s_tok[tid] = ((unsigned)t < T_TOKENS) ? t : 0;
    }
    __syncthreads();

    const __half* w1e = g_w1t + (size_t)e * FDIM * DDIM + (size_t)n0 * DDIM;
    const ptrdiff_t d31 = (const char*)g_w3t - (const char*)g_w1t;

    const char* srcA[4]; const char* srcB1[2];
    uint32_t dOfA[4], dOfB[2];
#pragma unroll
    for (int i = 0; i < 4; i++) {
        int idx = tid + i * 256;
        int row = idx >> 3, c = idx & 7;
        dOfA[i] = (uint32_t)(row * 128 + ((c * 16) ^ ((row & 7) << 4)));
        srcA[i] = (const char*)(g_xt + (size_t)s_tok[row] * DDIM + c * 8);
    }
#pragma unroll
    for (int i = 0; i < 2; i++) {
        int idx = tid + i * 256;
        int row = idx >> 3, c = idx & 7;
        dOfB[i] = (uint32_t)(row * 128 + ((c * 16) ^ ((row & 7) << 4)));
        srcB1[i] = (const char*)(w1e + (size_t)row * DDIM + c * 8);
    }

    float accU[4][2][4], accV[4][2][4];
#pragma unroll
    for (int i = 0; i < 4; i++)
#pragma unroll
        for (int j = 0; j < 2; j++)
#pragma unroll
            for (int q = 0; q < 4; q++) { accU[i][j][q] = 0.f; accV[i][j][q] = 0.f; }

    const int KS = DDIM / BK;   // 16

#define G1_ISSUE(s)                                                            \
    do {                                                                       \
        uint32_t base_ = sb + 1024 + ((s) % 3) * STAGE1_SZ;                    \
        size_t off_ = (size_t)(s) * 128;                                       \
        _Pragma("unroll")                                                      \
        for (int i_ = 0; i_ < 4; i_++)                                         \
            CP_ASYNC16(base_ + dOfA[i_], srcA[i_] + off_);                     \
        _Pragma("unroll")                                                      \
        for (int i_ = 0; i_ < 2; i_++) {                                       \
            CP_ASYNC16(base_ + 16384 + dOfB[i_], srcB1[i_] + off_);            \
            CP_ASYNC16(base_ + 24576 + dOfB[i_], srcB1[i_] + d31 + off_);      \
        }                                                                      \
    } while (0)

    G1_ISSUE(0); CP_COMMIT();
    G1_ISSUE(1); CP_COMMIT();

    for (int ks = 0; ks < KS; ks++) {
        CP_WAIT1();
        __syncthreads();
        if (ks + 2 < KS) G1_ISSUE(ks + 2);
        CP_COMMIT();

        const uint32_t sA  = sb + 1024 + (ks % 3) * STAGE1_SZ;
        const uint32_t sB1 = sA + 16384;
        const uint32_t sB3 = sA + 24576;
#pragma unroll
        for (int g = 0; g < 4; g++) {
            const uint32_t kb = (uint32_t)(g * 32 + 4 * c4);
            const uint32_t k0 = kb ^ xa;
            const uint32_t k1 = (kb + 16) ^ xa;
            uint32_t a[4][4], b1f[2][2], b3f[2][2];
#pragma unroll
            for (int mt = 0; mt < 4; mt++) {
                uint32_t rowb = sA + (uint32_t)((wm * 64 + mt * 16 + r4) * 128);
                a[mt][0] = lds32(rowb + k0);
                a[mt][1] = lds32(rowb + 1024 + k0);
                a[mt][2] = lds32(rowb + k1);
                a[mt][3] = lds32(rowb + 1024 + k1);
            }
#pragma unroll
            for (int nt = 0; nt < 2; nt++) {
                uint32_t nrow = (uint32_t)((wn * 16 + nt * 8 + r4) * 128);
                b1f[nt][0] = lds32(sB1 + nrow + k0);
                b1f[nt][1] = lds32(sB1 + nrow + k1);
                b3f[nt][0] = lds32(sB3 + nrow + k0);
                b3f[nt][1] = lds32(sB3 + nrow + k1);
            }
#pragma unroll
            for (int nt = 0; nt < 2; nt++)
#pragma unroll
                for (int mt = 0; mt < 4; mt++) {
                    mma16(accU[mt][nt], a[mt], b1f[nt][0], b1f[nt][1]);
                    mma16(accV[mt][nt], a[mt], b3f[nt][0], b3f[nt][1]);
                }
        }
    }

#pragma unroll
    for (int mt = 0; mt < 4; mt++) {
#pragma unroll
        for (int nt = 0; nt < 2; nt++) {
#pragma unroll
            for (int half = 0; half < 2; half++) {
                int r = r0 + wm * 64 + mt * 16 + r4 + half * 8;
                int cgl = n0 + wn * 16 + nt * 8 + 2 * c4;
                float u0 = accU[mt][nt][2 * half],     v0 = accV[mt][nt][2 * half];
                float u1 = accU[mt][nt][2 * half + 1], v1 = accV[mt][nt][2 * half + 1];
                __half2 o = __floats2half2_rn(u0 / (1.f + __expf(-u0)) * v0,
                                              u1 / (1.f + __expf(-u1)) * v1);
                *(__half2*)(g_H + (size_t)r * FDIM + cgl) = o;
            }
        }
    }
}

// ---------------------------------------------------------------------------
// GEMM2 (split-K) — Yout = H[:, k_base:+2048] @ w2t[:, :, k_base:+2048]
// [fp16 MMA, BK=64, occ 2]
// ---------------------------------------------------------------------------
__global__ void __launch_bounds__(256, 2)
gemm2_kernel(int k_base, float* __restrict__ Yout) {
    if (blockIdx.x >= g_nmt) return;
    extern __shared__ char smem[];
    const uint32_t sb = smem_u32(smem);
    const int tid = threadIdx.x, wid = tid >> 5, lane = tid & 31;
    const int wm = wid >> 2, wn = wid & 3;
    const int r4 = lane >> 2, c4 = lane & 3;
    const uint32_t xa = (uint32_t)(r4 << 4);

    const int e  = g_tile_e[blockIdx.x];
    const int r0 = g_tile_r[blockIdx.x];
    const int n0 = blockIdx.y * 128;

    const __half* w2e = g_w2t + (size_t)e * DDIM * FDIM + (size_t)n0 * FDIM + k_base;

    const char* srcA[4]; const char* srcB[4];
    uint32_t dOf[4];
#pragma unroll
    for (int i = 0; i < 4; i++) {
        int idx = tid + i * 256;
        int row = idx >> 3, c = idx & 7;
        dOf[i] = (uint32_t)(row * 128 + ((c * 16) ^ ((row & 7) << 4)));
        srcA[i] = (const char*)(g_H + (size_t)(r0 + row) * FDIM + k_base + c * 8);
        srcB[i] = (const char*)(w2e + (size_t)row * FDIM + c * 8);
    }

    float acc[4][4][4];
#pragma unroll
    for (int i = 0; i < 4; i++)
#pragma unroll
        for (int j = 0; j < 4; j++)
#pragma unroll
            for (int q = 0; q < 4; q++) acc[i][j][q] = 0.f;

    const int KS = (FDIM / 2) / BK;   // 32

#define G2_ISSUE(s)                                                            \
    do {                                                                       \
        uint32_t base_ = sb + 1024 + ((s) % 3) * STAGE2_SZ;                    \
        size_t off_ = (size_t)(s) * 128;                                       \
        _Pragma("unroll")                                                      \
        for (int i_ = 0; i_ < 4; i_++) {                                       \
            CP_ASYNC16(base_ + dOf[i_],         srcA[i_] + off_);              \
            CP_ASYNC16(base_ + 16384 + dOf[i_], srcB[i_] + off_);              \
        }                                                                      \
    } while (0)

    G2_ISSUE(0); CP_COMMIT();
    G2_ISSUE(1); CP_COMMIT();

    for (int ks = 0; ks < KS; ks++) {
        CP_WAIT1();
        __syncthreads();
        if (ks + 2 < KS) G2_ISSUE(ks + 2);
        CP_COMMIT();

        const uint32_t sA = sb + 1024 + (ks % 3) * STAGE2_SZ;
        const uint32_t sB = sA + 16384;
#pragma unroll
        for (int g = 0; g < 4; g++) {
            const uint32_t kb = (uint32_t)(g * 32 + 4 * c4);
            const uint32_t k0 = kb ^ xa;
            const uint32_t k1 = (kb + 16) ^ xa;
            uint32_t a[4][4], bf[4][2];
#pragma unroll
            for (int mt = 0; mt < 4; mt++) {
                uint32_t rowb = sA + (uint32_t)((wm * 64 + mt * 16 + r4) * 128);
                a[mt][0] = lds32(rowb + k0);
                a[mt][1] = lds32(rowb + 1024 + k0);
                a[mt][2] = lds32(rowb + k1);
                a[mt][3] = lds32(rowb + 1024 + k1);
            }
#pragma unroll
            for (int nt = 0; nt < 4; nt++) {
                uint32_t nrow = (uint32_t)((wn * 32 + nt * 8 + r4) * 128);
                bf[nt][0] = lds32(sB + nrow + k0);
                bf[nt][1] = lds32(sB + nrow + k1);
            }
#pragma unroll
            for (int nt = 0; nt < 4; nt++)
#pragma unroll
                for (int mt = 0; mt < 4; mt++)
                    mma16(acc[mt][nt], a[mt], bf[nt][0], bf[nt][1]);
        }
    }

#pragma unroll
    for (int mt = 0; mt < 4; mt++) {
#pragma unroll
        for (int nt = 0; nt < 4; nt++) {
#pragma unroll
            for (int half = 0; half < 2; half++) {
                int r = r0 + wm * 64 + mt * 16 + r4 + half * 8;
                int cgl = n0 + wn * 32 + nt * 8 + 2 * c4;
                float2 o;
                o.x = acc[mt][nt][2 * half];
                o.y = acc[mt][nt][2 * half + 1];
                *(float2*)(Yout + (size_t)r * DDIM + cgl) = o;
            }
        }
    }
}

// ---------------------------------------------------------------------------
// combine — out[t] = w0*(Y1[r0]+Y2[r0]) + w1*(Y1[r1]+Y2[r1])
// ---------------------------------------------------------------------------
__global__ void combine_kernel(float* __restrict__ out) {
    int t = blockIdx.x;
    int d = threadIdx.x * 4;
    float w0 = g_tok_w[2 * t], w1v = g_tok_w[2 * t + 1];
    int   r0 = g_tok_row[2 * t], r1 = g_tok_row[2 * t + 1];
    const float4 a1 = *(const float4*)(g_Y1 + (size_t)r0 * DDIM + d);
    const float4 a2 = *(const float4*)(g_Y2 + (size_t)r0 * DDIM + d);
    const float4 b1 = *(const float4*)(g_Y1 + (size_t)r1 * DDIM + d);
    const float4 b2 = *(const float4*)(g_Y2 + (size_t)r1 * DDIM + d);
    float4 o;
    o.x = w0 * (a1.x + a2.x) + w1v * (b1.x + b2.x);
    o.y = w0 * (a1.y + a2.y) + w1v * (b1.y + b2.y);
    o.z = w0 * (a1.z + a2.z) + w1v * (b1.z + b2.z);
    o.w = w0 * (a1.w + a2.w) + w1v * (b1.w + b2.w);
    *(float4*)(out + (size_t)t * DDIM + d) = o;
}

// ---------------------------------------------------------------------------
// Launcher — ONE side stream (R10-proven pattern).
// s1: t13a, t13b, t2, gemm2a (after gemm1a event) — gemm2a || gemm1b.
// main: convx, router, gemm1a, gemm1b, gemm2b, combine.
// ---------------------------------------------------------------------------
extern "C" void kernel_launch(void* const* d_in, const int* in_sizes, int n_in,
                              void* d_out, int out_size) {
    const float* x  = (const float*)d_in[0];
    const float* rw = (const float*)d_in[1];
    const float* rb = (const float*)d_in[2];
    const float* w1 = (const float*)d_in[3];
    const float* w2 = (const float*)d_in[4];
    const float* w3 = (const float*)d_in[5];
    float* out = (float*)d_out;

    cudaFuncSetAttribute(gemm1_kernel, cudaFuncAttributeMaxDynamicSharedMemorySize, SMEM1_SZ);
    cudaFuncSetAttribute(gemm2_kernel, cudaFuncAttributeMaxDynamicSharedMemorySize, SMEM2_SZ);

    __half *w1t, *w3t, *w2t;
    float *y1, *y2;
    cudaGetSymbolAddress((void**)&w1t, g_w1t);
    cudaGetSymbolAddress((void**)&w3t, g_w3t);
    cudaGetSymbolAddress((void**)&w2t, g_w2t);
    cudaGetSymbolAddress((void**)&y1, g_Y1);
    cudaGetSymbolAddress((void**)&y2, g_Y2);

    cudaStream_t s1;
    cudaEvent_t e0, e13a, e13b, eg1a, eg2a;
    cudaStreamCreateWithFlags(&s1, cudaStreamNonBlocking);
    cudaEventCreateWithFlags(&e0,   cudaEventDisableTiming);
    cudaEventCreateWithFlags(&e13a, cudaEventDisableTiming);
    cudaEventCreateWithFlags(&e13b, cudaEventDisableTiming);
    cudaEventCreateWithFlags(&eg1a, cudaEventDisableTiming);
    cudaEventCreateWithFlags(&eg2a, cudaEventDisableTiming);

    cudaEventRecord(e0, 0);
    cudaStreamWaitEvent(s1, e0, 0);

    convx_init_kernel<<<(T_TOKENS * DDIM / 8) / 256, 256>>>(x);              // #1 main
    transpose13_kernel<<<dim3(64, DDIM / 32, 2 * NEXP), dim3(32, 8), 0, s1>>>(
        w1, w3, w1t, w3t, 0);                                                // #2 s1 (F 0..2047)
    cudaEventRecord(e13a, s1);
    router_fused_kernel<<<64, 256>>>(x, rw, rb);                             // #3 main

    cudaStreamWaitEvent(0, e13a, 0);
    gemm1_kernel<<<dim3(MAX_MT, 32), 256, SMEM1_SZ>>>(0);                    // #4 main (profiled)
    cudaEventRecord(eg1a, 0);

    transpose13_kernel<<<dim3(64, DDIM / 32, 2 * NEXP), dim3(32, 8), 0, s1>>>(
        w1, w3, w1t, w3t, 2048);                                             // #5 s1
    cudaEventRecord(e13b, s1);
    transpose2_kernel<<<dim3(DDIM / 32, FDIM / 32, NEXP), dim3(32, 8), 0, s1>>>(
        w2, w2t);                                                            // #6 s1

    // gemm2a on s1: consumes H[:, 0:2048]; ordered after t2 on s1, after gemm1a via event
    cudaStreamWaitEvent(s1, eg1a, 0);
    gemm2_kernel<<<dim3(MAX_MT, DDIM / 128), 256, SMEM2_SZ, s1>>>(0, y1);    // #7 s1 (|| gemm1b)
    cudaEventRecord(eg2a, s1);

    // gemm1b on main (needs t13b)
    cudaStreamWaitEvent(0, e13b, 0);
    gemm1_kernel<<<dim3(MAX_MT, 32), 256, SMEM1_SZ>>>(2048);                 // #8 main

    // gemm2b on main: consumes H[:, 2048:4096]; t2 already done before gemm2a on s1,
    // but main needs its own ordering — eg2a implies t2 complete.
    cudaStreamWaitEvent(0, eg2a, 0);
    gemm2_kernel<<<dim3(MAX_MT, DDIM / 128), 256, SMEM2_SZ>>>(2048, y2);     // #9 main

    combine_kernel<<<T_TOKENS, 256>>>(out);                                  // #10 main
}

// round 13
// speedup vs baseline: 2.3425x; 1.0734x over previous
#include <cuda_runtime.h>
#include <cuda_fp16.h>
#include <cstdint>

// ---------------------------------------------------------------------------
// Problem constants
// ---------------------------------------------------------------------------
#define T_TOKENS 4096
#define DDIM 1024
#define FDIM 4096
#define NEXP 8
#define BM 128
#define BK 64
#define MAX_MT 72
#define ROWS_CAP (MAX_MT * 128)

// ---------------------------------------------------------------------------
// Device scratch (fp16 operands, fp32 outputs)
// ---------------------------------------------------------------------------
__device__ int    g_cnt[NEXP];
__device__ int    g_cur[NEXP];
__device__ int    g_done;
__device__ int    g_nmt;
__device__ int    g_tile_e[MAX_MT];
__device__ int    g_tile_r[MAX_MT];
__device__ int    g_row_token[ROWS_CAP];
__device__ int    g_tok_e[T_TOKENS * 2];
__device__ int    g_tok_row[T_TOKENS * 2];
__device__ float  g_tok_w[T_TOKENS * 2];
__device__ __half g_H[(size_t)ROWS_CAP * FDIM];
__device__ float  g_Y1[(size_t)ROWS_CAP * DDIM];
__device__ float  g_Y2[(size_t)ROWS_CAP * DDIM];
__device__ __half g_xt[(size_t)T_TOKENS * DDIM];
__device__ __half g_w1t[(size_t)NEXP * DDIM * FDIM];
__device__ __half g_w3t[(size_t)NEXP * DDIM * FDIM];
__device__ __half g_w2t[(size_t)NEXP * DDIM * FDIM];

// ---------------------------------------------------------------------------
// Helpers
// ---------------------------------------------------------------------------
__device__ __forceinline__ uint32_t smem_u32(const void* p) {
    uint32_t a;
    asm("{ .reg .u64 t; cvta.to.shared.u64 t, %1; cvt.u32.u64 %0, t; }" : "=r"(a) : "l"(p));
    return a;
}
__device__ __forceinline__ uint32_t lds32(uint32_t a) {
    uint32_t v;
    asm volatile("ld.shared.b32 %0, [%1];" : "=r"(v) : "r"(a));
    return v;
}
__device__ __forceinline__ uint32_t h2u(__half2 h) {
    uint32_t u;
    __builtin_memcpy(&u, &h, 4);
    return u;
}
__device__ __forceinline__ void mma16(float* d, const uint32_t* a, uint32_t b0, uint32_t b1) {
    asm volatile(
        "mma.sync.aligned.m16n8k16.row.col.f32.f16.f16.f32 "
        "{%0,%1,%2,%3}, {%4,%5,%6,%7}, {%8,%9}, {%0,%1,%2,%3};"
        : "+f"(d[0]), "+f"(d[1]), "+f"(d[2]), "+f"(d[3])
        : "r"(a[0]), "r"(a[1]), "r"(a[2]), "r"(a[3]), "r"(b0), "r"(b1));
}
#define CP_ASYNC16(dst, src) \
    asm volatile("cp.async.cg.shared.global [%0], [%1], 16;" :: "r"(dst), "l"(src))
#define CP_COMMIT() asm volatile("cp.async.commit_group;" ::: "memory")
#define CP_WAIT1()  asm volatile("cp.async.wait_group 1;" ::: "memory")

// Rows: 128B (64 fp16), SW128 swizzle  off = r*128 + (b ^ ((r&7)<<4)).
// Conflict-free for staging chunks and fragment loads (verified R8-R12).
#define STAGE1_SZ 32768   // A(16K) + B1(8K) + B3(8K)
#define STAGE2_SZ 32768   // A(16K) + B(16K)
#define SMEM1_SZ (1024 + 3 * STAGE1_SZ)   // 99328/CTA, occ 2
#define SMEM2_SZ (1024 + 3 * STAGE2_SZ)

// ---------------------------------------------------------------------------
// init: zero routing counters
// ---------------------------------------------------------------------------
__global__ void init_kernel() {
    if (threadIdx.x < NEXP) g_cnt[threadIdx.x] = 0;
    if (threadIdx.x == NEXP) g_done = 0;
}

// ---------------------------------------------------------------------------
// router (+x->fp16 conversion) + scan + scatter (last-CTA pattern)
// 256 CTAs x 256 threads; each warp handles 2 tokens; converts x rows as it goes.
// ---------------------------------------------------------------------------
__global__ void __launch_bounds__(256)
router_fused_kernel(const float* __restrict__ x, const float* __restrict__ rw,
                    const float* __restrict__ rb) {
    __shared__ float s_rw[NEXP * DDIM];
    __shared__ int s_last;
    const int tid = threadIdx.x, wid = tid >> 5, lane = tid & 31;

    for (int i = tid; i < NEXP * DDIM / 2; i += 256)
        ((float2*)s_rw)[i] = ((const float2*)rw)[i];
    __syncthreads();

    const int tbase = blockIdx.x * 16 + wid * 2;
#pragma unroll
    for (int j = 0; j < 2; j++) {
        const int t = tbase + j;
        const float* xt = x + (size_t)t * DDIM;
        __half2* xo = (__half2*)(g_xt + (size_t)t * DDIM);
        float acc[NEXP];
#pragma unroll
        for (int e = 0; e < NEXP; e++) acc[e] = 0.f;
        for (int i = lane * 2; i < DDIM; i += 64) {
            const float2 xv = *(const float2*)(xt + i);
            xo[i >> 1] = __floats2half2_rn(xv.x, xv.y);
#pragma unroll
            for (int e = 0; e < NEXP; e++) {
                const float2 wv = *(const float2*)(s_rw + e * DDIM + i);
                acc[e] += xv.x * wv.x + xv.y * wv.y;
            }
        }
#pragma unroll
        for (int off = 16; off; off >>= 1)
#pragma unroll
            for (int e = 0; e < NEXP; e++) acc[e] += __shfl_xor_sync(0xffffffffu, acc[e], off);
        if (lane == 0) {
#pragma unroll
            for (int e = 0; e < NEXP; e++) acc[e] += rb[e];
            int e0 = 0; float l0 = acc[0];
#pragma unroll
            for (int e = 1; e < NEXP; e++) if (acc[e] > l0) { l0 = acc[e]; e0 = e; }
            int e1 = (e0 == 0) ? 1 : 0; float l1 = acc[e1];
#pragma unroll
            for (int e = 0; e < NEXP; e++)
                if (e != e0 && acc[e] > l1) { l1 = acc[e]; e1 = e; }
            float w0 = 1.f / (1.f + __expf(l1 - l0));
            g_tok_e[2 * t] = e0;  g_tok_e[2 * t + 1] = e1;
            g_tok_w[2 * t] = w0;  g_tok_w[2 * t + 1] = 1.f - w0;
            atomicAdd(&g_cnt[e0], 1);
            atomicAdd(&g_cnt[e1], 1);
        }
    }

    __syncthreads();
    if (tid == 0) {
        __threadfence();
        int v = atomicAdd(&g_done, 1);
        s_last = (v == (int)gridDim.x - 1);
    }
    __syncthreads();
    if (!s_last) return;
    __threadfence();

    if (tid == 0) {
        int base = 0, nt = 0;
        for (int e = 0; e < NEXP; e++) {
            g_cur[e] = base;
            int tiles = (g_cnt[e] + 127) >> 7;
            for (int i = 0; i < tiles; i++) { g_tile_e[nt] = e; g_tile_r[nt] = base + i * 128; nt++; }
            base += tiles << 7;
        }
        g_nmt = nt;
        g_done = 0;
    }
    __syncthreads();

    for (int t = tid; t < T_TOKENS; t += 256) {
#pragma unroll
        for (int k = 0; k < 2; k++) {
            int e = g_tok_e[2 * t + k];
            int r = atomicAdd(&g_cur[e], 1);
            g_row_token[r] = t;
            g_tok_row[2 * t + k] = r;
        }
    }
}

// ---------------------------------------------------------------------------
// Weight transposes (+fp16 convert) — forked stream; transpose13 split by F-half
// ---------------------------------------------------------------------------
__global__ void transpose13_kernel(const float* __restrict__ w1, const float* __restrict__ w3,
                                   __half* __restrict__ w1t, __half* __restrict__ w3t,
                                   int c_base) {
    __shared__ float t[32][33];
    const int zz = blockIdx.z;
    const float* src = (zz < NEXP) ? w1 : w3;
    __half* dst = (zz < NEXP) ? w1t : w3t;
    const size_t mo = (size_t)(zz & 7) * DDIM * FDIM;
    const int c0 = c_base + blockIdx.x * 32, r0 = blockIdx.y * 32;
    const int tx = threadIdx.x, ty = threadIdx.y;
#pragma unroll
    for (int i = 0; i < 32; i += 8)
        t[ty + i][tx] = src[mo + (size_t)(r0 + ty + i) * FDIM + c0 + tx];
    __syncthreads();
#pragma unroll
    for (int i = 0; i < 32; i += 8)
        dst[mo + (size_t)(c0 + ty + i) * DDIM + r0 + tx] = __float2half_rn(t[tx][ty + i]);
}

__global__ void transpose2_kernel(const float* __restrict__ src, __half* __restrict__ dst) {
    __shared__ float t[32][33];
    const size_t mo = (size_t)blockIdx.z * DDIM * FDIM;
    const int c0 = blockIdx.x * 32, r0 = blockIdx.y * 32;
    const int tx = threadIdx.x, ty = threadIdx.y;
#pragma unroll
    for (int i = 0; i < 32; i += 8)
        t[ty + i][tx] = src[mo + (size_t)(r0 + ty + i) * DDIM + c0 + tx];
    __syncthreads();
#pragma unroll
    for (int i = 0; i < 32; i += 8)
        dst[mo + (size_t)(c0 + ty + i) * FDIM + r0 + tx] = __float2half_rn(t[tx][ty + i]);
}

// ---------------------------------------------------------------------------
// GEMM1 — H = silu(X@w1) * (X@w3)   [fp16 MMA, BK=64, occ 2]  (R12-identical)
// ---------------------------------------------------------------------------
__global__ void __launch_bounds__(256, 2)
gemm1_kernel(int n_base) {
    if (blockIdx.x >= g_nmt) return;
    extern __shared__ char smem[];
    const uint32_t sb = smem_u32(smem);
    const int tid = threadIdx.x, wid = tid >> 5, lane = tid & 31;
    const int wm = wid >> 2, wn = wid & 3;
    const int r4 = lane >> 2, c4 = lane & 3;
    const uint32_t xa = (uint32_t)(r4 << 4);

    const int e  = g_tile_e[blockIdx.x];
    const int r0 = g_tile_r[blockIdx.x];
    const int n0 = n_base + blockIdx.y * 64;

    int* s_tok = (int*)smem;
    if (tid < 128) {
        int t = g_row_token[r0 + tid];
        s_tok[tid] = ((unsigned)t < T_TOKENS) ? t : 0;
    }
    __syncthreads();

    const __half* w1e = g_w1t + (size_t)e * FDIM * DDIM + (size_t)n0 * DDIM;
    const ptrdiff_t d31 = (const char*)g_w3t - (const char*)g_w1t;

    const char* srcA[4]; const char* srcB1[2];
    uint32_t dOfA[4], dOfB[2];
#pragma unroll
    for (int i = 0; i < 4; i++) {
        int idx = tid + i * 256;
        int row = idx >> 3, c = idx & 7;
        dOfA[i] = (uint32_t)(row * 128 + ((c * 16) ^ ((row & 7) << 4)));
        srcA[i] = (const char*)(g_xt + (size_t)s_tok[row] * DDIM + c * 8);
    }
#pragma unroll
    for (int i = 0; i < 2; i++) {
        int idx = tid + i * 256;
        int row = idx >> 3, c = idx & 7;
        dOfB[i] = (uint32_t)(row * 128 + ((c * 16) ^ ((row & 7) << 4)));
        srcB1[i] = (const char*)(w1e + (size_t)row * DDIM + c * 8);
    }

    float accU[4][2][4], accV[4][2][4];
#pragma unroll
    for (int i = 0; i < 4; i++)
#pragma unroll
        for (int j = 0; j < 2; j++)
#pragma unroll
            for (int q = 0; q < 4; q++) { accU[i][j][q] = 0.f; accV[i][j][q] = 0.f; }

    const int KS = DDIM / BK;   // 16

#define G1_ISSUE(s)                                                            \
    do {                                                                       \
        uint32_t base_ = sb + 1024 + ((s) % 3) * STAGE1_SZ;                    \
        size_t off_ = (size_t)(s) * 128;                                       \
        _Pragma("unroll")                                                      \
        for (int i_ = 0; i_ < 4; i_++)                                         \
            CP_ASYNC16(base_ + dOfA[i_], srcA[i_] + off_);                     \
        _Pragma("unroll")                                                      \
        for (int i_ = 0; i_ < 2; i_++) {                                       \
            CP_ASYNC16(base_ + 16384 + dOfB[i_], srcB1[i_] + off_);            \
            CP_ASYNC16(base_ + 24576 + dOfB[i_], srcB1[i_] + d31 + off_);      \
        }                                                                      \
    } while (0)

    G1_ISSUE(0); CP_COMMIT();
    G1_ISSUE(1); CP_COMMIT();

    for (int ks = 0; ks < KS; ks++) {
        CP_WAIT1();
        __syncthreads();
        if (ks + 2 < KS) G1_ISSUE(ks + 2);
        CP_COMMIT();

        const uint32_t sA  = sb + 1024 + (ks % 3) * STAGE1_SZ;
        const uint32_t sB1 = sA + 16384;
        const uint32_t sB3 = sA + 24576;
#pragma unroll
        for (int g = 0; g < 4; g++) {
            const uint32_t kb = (uint32_t)(g * 32 + 4 * c4);
            const uint32_t k0 = kb ^ xa;
            const uint32_t k1 = (kb + 16) ^ xa;
            uint32_t a[4][4], b1f[2][2], b3f[2][2];
#pragma unroll
            for (int mt = 0; mt < 4; mt++) {
                uint32_t rowb = sA + (uint32_t)((wm * 64 + mt * 16 + r4) * 128);
                a[mt][0] = lds32(rowb + k0);
                a[mt][1] = lds32(rowb + 1024 + k0);
                a[mt][2] = lds32(rowb + k1);
                a[mt][3] = lds32(rowb + 1024 + k1);
            }
#pragma unroll
            for (int nt = 0; nt < 2; nt++) {
                uint32_t nrow = (uint32_t)((wn * 16 + nt * 8 + r4) * 128);
                b1f[nt][0] = lds32(sB1 + nrow + k0);
                b1f[nt][1] = lds32(sB1 + nrow + k1);
                b3f[nt][0] = lds32(sB3 + nrow + k0);
                b3f[nt][1] = lds32(sB3 + nrow + k1);
            }
#pragma unroll
            for (int nt = 0; nt < 2; nt++)
#pragma unroll
                for (int mt = 0; mt < 4; mt++) {
                    mma16(accU[mt][nt], a[mt], b1f[nt][0], b1f[nt][1]);
                    mma16(accV[mt][nt], a[mt], b3f[nt][0], b3f[nt][1]);
                }
        }
    }

#pragma unroll
    for (int mt = 0; mt < 4; mt++) {
#pragma unroll
        for (int nt = 0; nt < 2; nt++) {
#pragma unroll
            for (int half = 0; half < 2; half++) {
                int r = r0 + wm * 64 + mt * 16 + r4 + half * 8;
                int cgl = n0 + wn * 16 + nt * 8 + 2 * c4;
                float u0 = accU[mt][nt][2 * half],     v0 = accV[mt][nt][2 * half];
                float u1 = accU[mt][nt][2 * half + 1], v1 = accV[mt][nt][2 * half + 1];
                __half2 o = __floats2half2_rn(u0 / (1.f + __expf(-u0)) * v0,
                                              u1 / (1.f + __expf(-u1)) * v1);
                *(__half2*)(g_H + (size_t)r * FDIM + cgl) = o;
            }
        }
    }
}

// ---------------------------------------------------------------------------
// GEMM2 (split-K) — Yout = H[:, k_base:+2048] @ w2t[:, :, k_base:+2048]
// [fp16 MMA, BK=64, occ 2]  (R12-identical)
// ---------------------------------------------------------------------------
__global__ void __launch_bounds__(256, 2)
gemm2_kernel(int k_base, float* __restrict__ Yout) {
    if (blockIdx.x >= g_nmt) return;
    extern __shared__ char smem[];
    const uint32_t sb = smem_u32(smem);
    const int tid = threadIdx.x, wid = tid >> 5, lane = tid & 31;
    const int wm = wid >> 2, wn = wid & 3;
    const int r4 = lane >> 2, c4 = lane & 3;
    const uint32_t xa = (uint32_t)(r4 << 4);

    const int e  = g_tile_e[blockIdx.x];
    const int r0 = g_tile_r[blockIdx.x];
    const int n0 = blockIdx.y * 128;

    const __half* w2e = g_w2t + (size_t)e * DDIM * FDIM + (size_t)n0 * FDIM + k_base;

    const char* srcA[4]; const char* srcB[4];
    uint32_t dOf[4];
#pragma unroll
    for (int i = 0; i < 4; i++) {
        int idx = tid + i * 256;
        int row = idx >> 3, c = idx & 7;
        dOf[i] = (uint32_t)(row * 128 + ((c * 16) ^ ((row & 7) << 4)));
        srcA[i] = (const char*)(g_H + (size_t)(r0 + row) * FDIM + k_base + c * 8);
        srcB[i] = (const char*)(w2e + (size_t)row * FDIM + c * 8);
    }

    float acc[4][4][4];
#pragma unroll
    for (int i = 0; i < 4; i++)
#pragma unroll
        for (int j = 0; j < 4; j++)
#pragma unroll
            for (int q = 0; q < 4; q++) acc[i][j][q] = 0.f;

    const int KS = (FDIM / 2) / BK;   // 32

#define G2_ISSUE(s)                                                            \
    do {                                                                       \
        uint32_t base_ = sb + 1024 + ((s) % 3) * STAGE2_SZ;                    \
        size_t off_ = (size_t)(s) * 128;                                       \
        _Pragma("unroll")                                                      \
        for (int i_ = 0; i_ < 4; i_++) {                                       \
            CP_ASYNC16(base_ + dOf[i_],         srcA[i_] + off_);              \
            CP_ASYNC16(base_ + 16384 + dOf[i_], srcB[i_] + off_);              \
        }                                                                      \
    } while (0)

    G2_ISSUE(0); CP_COMMIT();
    G2_ISSUE(1); CP_COMMIT();

    for (int ks = 0; ks < KS; ks++) {
        CP_WAIT1();
        __syncthreads();
        if (ks + 2 < KS) G2_ISSUE(ks + 2);
        CP_COMMIT();

        const uint32_t sA = sb + 1024 + (ks % 3) * STAGE2_SZ;
        const uint32_t sB = sA + 16384;
#pragma unroll
        for (int g = 0; g < 4; g++) {
            const uint32_t kb = (uint32_t)(g * 32 + 4 * c4);
            const uint32_t k0 = kb ^ xa;
            const uint32_t k1 = (kb + 16) ^ xa;
            uint32_t a[4][4], bf[4][2];
#pragma unroll
            for (int mt = 0; mt < 4; mt++) {
                uint32_t rowb = sA + (uint32_t)((wm * 64 + mt * 16 + r4) * 128);
                a[mt][0] = lds32(rowb + k0);
                a[mt][1] = lds32(rowb + 1024 + k0);
                a[mt][2] = lds32(rowb + k1);
                a[mt][3] = lds32(rowb + 1024 + k1);
            }
#pragma unroll
            for (int nt = 0; nt < 4; nt++) {
                uint32_t nrow = (uint32_t)((wn * 32 + nt * 8 + r4) * 128);
                bf[nt][0] = lds32(sB + nrow + k0);
                bf[nt][1] = lds32(sB + nrow + k1);
            }
#pragma unroll
            for (int nt = 0; nt < 4; nt++)
#pragma unroll
                for (int mt = 0; mt < 4; mt++)
                    mma16(acc[mt][nt], a[mt], bf[nt][0], bf[nt][1]);
        }
    }

#pragma unroll
    for (int mt = 0; mt < 4; mt++) {
#pragma unroll
        for (int nt = 0; nt < 4; nt++) {
#pragma unroll
            for (int half = 0; half < 2; half++) {
                int r = r0 + wm * 64 + mt * 16 + r4 + half * 8;
                int cgl = n0 + wn * 32 + nt * 8 + 2 * c4;
                float2 o;
                o.x = acc[mt][nt][2 * half];
                o.y = acc[mt][nt][2 * half + 1];
                *(float2*)(Yout + (size_t)r * DDIM + cgl) = o;
            }
        }
    }
}

// ---------------------------------------------------------------------------
// combine — out[t] = w0*(Y1[r0]+Y2[r0]) + w1*(Y1[r1]+Y2[r1])
// ---------------------------------------------------------------------------
__global__ void combine_kernel(float* __restrict__ out) {
    int t = blockIdx.x;
    int d = threadIdx.x * 4;
    float w0 = g_tok_w[2 * t], w1v = g_tok_w[2 * t + 1];
    int   r0 = g_tok_row[2 * t], r1 = g_tok_row[2 * t + 1];
    const float4 a1 = *(const float4*)(g_Y1 + (size_t)r0 * DDIM + d);
    const float4 a2 = *(const float4*)(g_Y2 + (size_t)r0 * DDIM + d);
    const float4 b1 = *(const float4*)(g_Y1 + (size_t)r1 * DDIM + d);
    const float4 b2 = *(const float4*)(g_Y2 + (size_t)r1 * DDIM + d);
    float4 o;
    o.x = w0 * (a1.x + a2.x) + w1v * (b1.x + b2.x);
    o.y = w0 * (a1.y + a2.y) + w1v * (b1.y + b2.y);
    o.z = w0 * (a1.z + a2.z) + w1v * (b1.z + b2.z);
    o.w = w0 * (a1.w + a2.w) + w1v * (b1.w + b2.w);
    *(float4*)(out + (size_t)t * DDIM + d) = o;
}

// ---------------------------------------------------------------------------
// Launcher — one side stream.
// s1: t13a, t13b, t2, gemm2a — gemm2a || gemm1b.
// main: init, router(+convx), gemm1a, gemm1b, gemm2b, combine.
// ---------------------------------------------------------------------------
extern "C" void kernel_launch(void* const* d_in, const int* in_sizes, int n_in,
                              void* d_out, int out_size) {
    const float* x  = (const float*)d_in[0];
    const float* rw = (const float*)d_in[1];
    const float* rb = (const float*)d_in[2];
    const float* w1 = (const float*)d_in[3];
    const float* w2 = (const float*)d_in[4];
    const float* w3 = (const float*)d_in[5];
    float* out = (float*)d_out;

    cudaFuncSetAttribute(gemm1_kernel, cudaFuncAttributeMaxDynamicSharedMemorySize, SMEM1_SZ);
    cudaFuncSetAttribute(gemm2_kernel, cudaFuncAttributeMaxDynamicSharedMemorySize, SMEM2_SZ);

    __half *w1t, *w3t, *w2t;
    float *y1, *y2;
    cudaGetSymbolAddress((void**)&w1t, g_w1t);
    cudaGetSymbolAddress((void**)&w3t, g_w3t);
    cudaGetSymbolAddress((void**)&w2t, g_w2t);
    cudaGetSymbolAddress((void**)&y1, g_Y1);
    cudaGetSymbolAddress((void**)&y2, g_Y2);

    cudaStream_t s1;
    cudaEvent_t e0, e13a, e13b, et2, eg1a;
    cudaStreamCreateWithFlags(&s1, cudaStreamNonBlocking);
    cudaEventCreateWithFlags(&e0,   cudaEventDisableTiming);
    cudaEventCreateWithFlags(&e13a, cudaEventDisableTiming);
    cudaEventCreateWithFlags(&e13b, cudaEventDisableTiming);
    cudaEventCreateWithFlags(&et2,  cudaEventDisableTiming);
    cudaEventCreateWithFlags(&eg1a, cudaEventDisableTiming);

    cudaEventRecord(e0, 0);
    cudaStreamWaitEvent(s1, e0, 0);

    init_kernel<<<1, 32>>>();                                                // #1 main
    transpose13_kernel<<<dim3(64, DDIM / 32, 2 * NEXP), dim3(32, 8), 0, s1>>>(
        w1, w3, w1t, w3t, 0);                                                // #2 s1 (F 0..2047)
    cudaEventRecord(e13a, s1);
    router_fused_kernel<<<256, 256>>>(x, rw, rb);                            // #3 main (+x->fp16)

    cudaStreamWaitEvent(0, e13a, 0);
    gemm1_kernel<<<dim3(MAX_MT, 32), 256, SMEM1_SZ>>>(0);                    // #4 main (profiled)
    cudaEventRecord(eg1a, 0);

    transpose13_kernel<<<dim3(64, DDIM / 32, 2 * NEXP), dim3(32, 8), 0, s1>>>(
        w1, w3, w1t, w3t, 2048);                                             // #5 s1
    cudaEventRecord(e13b, s1);
    transpose2_kernel<<<dim3(DDIM / 32, FDIM / 32, NEXP), dim3(32, 8), 0, s1>>>(
        w2, w2t);                                                            // #6 s1
    cudaEventRecord(et2, s1);

    // gemm2a on s1: consumes H[:, 0:2048]; ordered after t2 on s1, after gemm1a via event
    cudaStreamWaitEvent(s1, eg1a, 0);
    gemm2_kernel<<<dim3(MAX_MT, DDIM / 128), 256, SMEM2_SZ, s1>>>(0, y1);    // #7 s1 (|| gemm1b)

    // gemm1b on main (needs t13b)
    cudaStreamWaitEvent(0, e13b, 0);
    gemm1_kernel<<<dim3(MAX_MT, 32), 256, SMEM1_SZ>>>(2048);                 // #8 main

    // gemm2b on main: needs gemm1b (main order) + t2 (et2) — no false dep on gemm2a
    cudaStreamWaitEvent(0, et2, 0);
    gemm2_kernel<<<dim3(MAX_MT, DDIM / 128), 256, SMEM2_SZ>>>(2048, y2);     // #9 main

    // combine: needs gemm2b (main order) + gemm2a (s1) — join s1
    cudaEvent_t eg2a;
    cudaEventCreateWithFlags(&eg2a, cudaEventDisableTiming);
    cudaEventRecord(eg2a, s1);
    cudaStreamWaitEvent(0, eg2a, 0);
    combine_kernel<<<T_TOKENS, 256>>>(out);                                  // #10 main
}